// round 2
// baseline (speedup 1.0000x reference)
#include <cuda_runtime.h>
#include <cuda_bf16.h>

#define D_MODEL  1024
#define N_HEADS  16
#define HEAD_DIM 64
#define BATCH    2
#define SEQ      2048
#define NTOK     (BATCH * SEQ)   // 4096

// Scratch (no cudaMalloc allowed)
__device__ float g_q [NTOK * D_MODEL];
__device__ float g_k [NTOK * D_MODEL];
__device__ float g_v [NTOK * D_MODEL];
__device__ float g_ao[NTOK * D_MODEL];

// ---------------------------------------------------------------------------
// C[N,D] = A[N,K] * B[D,K]^T   (both operands K-contiguous, "NT" gemm)
// 128x128 tile, BK=8, 256 threads, 8x8 per thread.
// ---------------------------------------------------------------------------
__global__ __launch_bounds__(256) void sgemm_nt(
    const float* __restrict__ A,
    const float* __restrict__ B,
    float* __restrict__ C,
    int N, int D, int K)
{
    __shared__ float As[8][128];
    __shared__ float Bs[8][128];

    const int tid = threadIdx.x;
    const int m0 = blockIdx.y * 128;
    const int n0 = blockIdx.x * 128;

    const int lr = tid >> 1;          // 0..127: row within tile
    const int lk = (tid & 1) * 4;     // 0 or 4: k offset (float4)

    const float* Ap = A + (size_t)(m0 + lr) * K + lk;
    const float* Bp = B + (size_t)(n0 + lr) * K + lk;

    const int ty = tid >> 4;          // 0..15
    const int tx = tid & 15;          // 0..15

    float acc[8][8];
#pragma unroll
    for (int i = 0; i < 8; i++)
#pragma unroll
        for (int j = 0; j < 8; j++) acc[i][j] = 0.f;

    for (int k0 = 0; k0 < K; k0 += 8) {
        float4 a4 = *(const float4*)(Ap + k0);
        float4 b4 = *(const float4*)(Bp + k0);
        __syncthreads();   // previous iteration's readers done
        As[lk + 0][lr] = a4.x; As[lk + 1][lr] = a4.y;
        As[lk + 2][lr] = a4.z; As[lk + 3][lr] = a4.w;
        Bs[lk + 0][lr] = b4.x; Bs[lk + 1][lr] = b4.y;
        Bs[lk + 2][lr] = b4.z; Bs[lk + 3][lr] = b4.w;
        __syncthreads();

#pragma unroll
        for (int kk = 0; kk < 8; kk++) {
            float ra[8], rb[8];
            *(float4*)&ra[0] = *(const float4*)&As[kk][ty * 8];
            *(float4*)&ra[4] = *(const float4*)&As[kk][ty * 8 + 4];
            *(float4*)&rb[0] = *(const float4*)&Bs[kk][tx * 8];
            *(float4*)&rb[4] = *(const float4*)&Bs[kk][tx * 8 + 4];
#pragma unroll
            for (int i = 0; i < 8; i++)
#pragma unroll
                for (int j = 0; j < 8; j++)
                    acc[i][j] += ra[i] * rb[j];
        }
    }

    float* Cp = C + (size_t)(m0 + ty * 8) * D + n0 + tx * 8;
#pragma unroll
    for (int i = 0; i < 8; i++) {
        *(float4*)(Cp + (size_t)i * D)     = make_float4(acc[i][0], acc[i][1], acc[i][2], acc[i][3]);
        *(float4*)(Cp + (size_t)i * D + 4) = make_float4(acc[i][4], acc[i][5], acc[i][6], acc[i][7]);
    }
}

// ---------------------------------------------------------------------------
// Flash attention, fp32. grid = (SEQ/64, N_HEADS, BATCH), 256 threads.
// Each warp owns 8 query rows. Lane layout: r = lane>>2 (row), c4 = lane&3.
// Each lane: 16 score columns (c4*16+i), 16 output dims (c4*16+j).
// ---------------------------------------------------------------------------
__global__ __launch_bounds__(256) void flash_attn(
    const float* __restrict__ Q,
    const float* __restrict__ K,
    const float* __restrict__ V,
    float* __restrict__ O)
{
    __shared__ float Qs[64][64];
    __shared__ float Ks[64][64];
    __shared__ float Vs[64][64];

    const int qb   = blockIdx.x;          // 0..31
    const int h    = blockIdx.y;
    const int b    = blockIdx.z;
    const int tid  = threadIdx.x;
    const int warp = tid >> 5;
    const int lane = tid & 31;
    const int r    = lane >> 2;
    const int c4   = lane & 3;
    const int rg   = warp * 8 + r;        // q row within tile
    const int qglob = qb * 64 + rg;

    const size_t base = ((size_t)b * SEQ) * D_MODEL + (size_t)h * HEAD_DIM;

    // Load Q tile (pre-scaled by 1/sqrt(HEAD_DIM))
    for (int i = tid; i < 64 * 16; i += 256) {
        int row = i >> 4, d4 = i & 15;
        float4 qv = *(const float4*)(Q + base + (size_t)(qb * 64 + row) * D_MODEL + d4 * 4);
        qv.x *= 0.125f; qv.y *= 0.125f; qv.z *= 0.125f; qv.w *= 0.125f;
        *(float4*)&Qs[row][d4 * 4] = qv;
    }

    float m = -1e30f, l = 0.f;
    float acc[16];
#pragma unroll
    for (int j = 0; j < 16; j++) acc[j] = 0.f;

    for (int kb = 0; kb <= qb; kb++) {
        __syncthreads();   // previous iteration's readers of Ks/Vs done (also fences Qs on iter 0)
        for (int i = tid; i < 64 * 16; i += 256) {
            int row = i >> 4, d4 = i & 15;
            float4 kv = *(const float4*)(K + base + (size_t)(kb * 64 + row) * D_MODEL + d4 * 4);
            *(float4*)&Ks[row][d4 * 4] = kv;
            float4 vv = *(const float4*)(V + base + (size_t)(kb * 64 + row) * D_MODEL + d4 * 4);
            *(float4*)&Vs[row][d4 * 4] = vv;
        }
        __syncthreads();

        // --- scores: s[i] = q[rg] . k[c4*16+i] ---
        float s[16];
#pragma unroll
        for (int i = 0; i < 16; i++) s[i] = 0.f;
#pragma unroll
        for (int d4 = 0; d4 < 16; d4++) {
            float4 qv = *(const float4*)&Qs[rg][d4 * 4];
#pragma unroll
            for (int i = 0; i < 16; i++) {
                float4 kv = *(const float4*)&Ks[c4 * 16 + i][d4 * 4];
                s[i] += qv.x * kv.x + qv.y * kv.y + qv.z * kv.z + qv.w * kv.w;
            }
        }

        // --- causal mask (only diagonal block needs it) ---
        if (kb == qb) {
#pragma unroll
            for (int i = 0; i < 16; i++) {
                int kg = kb * 64 + c4 * 16 + i;
                if (kg > qglob) s[i] = -1e30f;
            }
        }

        // --- online softmax update (reduce across the 4 lanes of each row) ---
        float mnew = m;
#pragma unroll
        for (int i = 0; i < 16; i++) mnew = fmaxf(mnew, s[i]);
        mnew = fmaxf(mnew, __shfl_xor_sync(0xffffffffu, mnew, 1));
        mnew = fmaxf(mnew, __shfl_xor_sync(0xffffffffu, mnew, 2));

        float alpha = __expf(m - mnew);
        float psum = 0.f;
#pragma unroll
        for (int i = 0; i < 16; i++) { s[i] = __expf(s[i] - mnew); psum += s[i]; }
        psum += __shfl_xor_sync(0xffffffffu, psum, 1);
        psum += __shfl_xor_sync(0xffffffffu, psum, 2);
        l = l * alpha + psum;
        m = mnew;
#pragma unroll
        for (int j = 0; j < 16; j++) acc[j] *= alpha;

        // --- PV: acc[j] += sum_c p[c] * V[c][c4*16+j]; p for col block cq held by lane (r*4+cq) ---
#pragma unroll
        for (int cq = 0; cq < 4; cq++) {
#pragma unroll
            for (int i = 0; i < 16; i++) {
                float pv = __shfl_sync(0xffffffffu, s[i], (lane & ~3) | cq);
                int c = cq * 16 + i;
                const float4* vr = (const float4*)&Vs[c][c4 * 16];
#pragma unroll
                for (int j4 = 0; j4 < 4; j4++) {
                    float4 vv = vr[j4];
                    acc[j4 * 4 + 0] += pv * vv.x;
                    acc[j4 * 4 + 1] += pv * vv.y;
                    acc[j4 * 4 + 2] += pv * vv.z;
                    acc[j4 * 4 + 3] += pv * vv.w;
                }
            }
        }
    }

    // --- normalize and write ---
    float inv = 1.f / l;
    float* orow = O + base + (size_t)qglob * D_MODEL + c4 * 16;
#pragma unroll
    for (int j4 = 0; j4 < 4; j4++) {
        float4 ov = make_float4(acc[j4 * 4 + 0] * inv, acc[j4 * 4 + 1] * inv,
                                acc[j4 * 4 + 2] * inv, acc[j4 * 4 + 3] * inv);
        *(float4*)(orow + j4 * 4) = ov;
    }
}

// ---------------------------------------------------------------------------
extern "C" void kernel_launch(void* const* d_in, const int* in_sizes, int n_in,
                              void* d_out, int out_size)
{
    const float* x  = (const float*)d_in[0];
    const float* wq = (const float*)d_in[1];
    const float* wk = (const float*)d_in[2];
    const float* wv = (const float*)d_in[3];
    const float* wo = (const float*)d_in[4];
    float* out = (float*)d_out;

    float *q, *k, *v, *ao;
    cudaGetSymbolAddress((void**)&q,  g_q);
    cudaGetSymbolAddress((void**)&k,  g_k);
    cudaGetSymbolAddress((void**)&v,  g_v);
    cudaGetSymbolAddress((void**)&ao, g_ao);

    dim3 gg(D_MODEL / 128, NTOK / 128);   // (8, 32)
    sgemm_nt<<<gg, 256>>>(x, wq, q, NTOK, D_MODEL, D_MODEL);
    sgemm_nt<<<gg, 256>>>(x, wk, k, NTOK, D_MODEL, D_MODEL);
    sgemm_nt<<<gg, 256>>>(x, wv, v, NTOK, D_MODEL, D_MODEL);

    dim3 ga(SEQ / 64, N_HEADS, BATCH);    // (32, 16, 2)
    flash_attn<<<ga, 256>>>(q, k, v, ao);

    sgemm_nt<<<gg, 256>>>(ao, wo, out, NTOK, D_MODEL, D_MODEL);
}

// round 3
// speedup vs baseline: 2.3244x; 2.3244x over previous
#include <cuda_runtime.h>
#include <cuda_bf16.h>

#define D_MODEL  1024
#define N_HEADS  16
#define HEAD_DIM 64
#define BATCH    2
#define SEQ      2048
#define NTOK     (BATCH * SEQ)   // 4096
#define FULLMASK 0xffffffffu

// Scratch (no cudaMalloc allowed)
__device__ float g_q [NTOK * D_MODEL];
__device__ float g_k [NTOK * D_MODEL];
__device__ float g_v [NTOK * D_MODEL];
__device__ float g_ao[NTOK * D_MODEL];

// ---------------------------------------------------------------------------
// fp32 GEMM: C[N,D] = A[N,K] * B[D,K]^T  (128x128 tile, BK=8, 256 thr)
// ---------------------------------------------------------------------------
__global__ __launch_bounds__(256) void sgemm_nt(
    const float* __restrict__ A,
    const float* __restrict__ B,
    float* __restrict__ C,
    int N, int D, int K)
{
    __shared__ float As[8][128];
    __shared__ float Bs[8][128];

    const int tid = threadIdx.x;
    const int m0 = blockIdx.y * 128;
    const int n0 = blockIdx.x * 128;

    const int lr = tid >> 1;
    const int lk = (tid & 1) * 4;

    const float* Ap = A + (size_t)(m0 + lr) * K + lk;
    const float* Bp = B + (size_t)(n0 + lr) * K + lk;

    const int ty = tid >> 4;
    const int tx = tid & 15;

    float acc[8][8];
#pragma unroll
    for (int i = 0; i < 8; i++)
#pragma unroll
        for (int j = 0; j < 8; j++) acc[i][j] = 0.f;

    for (int k0 = 0; k0 < K; k0 += 8) {
        float4 a4 = *(const float4*)(Ap + k0);
        float4 b4 = *(const float4*)(Bp + k0);
        __syncthreads();
        As[lk + 0][lr] = a4.x; As[lk + 1][lr] = a4.y;
        As[lk + 2][lr] = a4.z; As[lk + 3][lr] = a4.w;
        Bs[lk + 0][lr] = b4.x; Bs[lk + 1][lr] = b4.y;
        Bs[lk + 2][lr] = b4.z; Bs[lk + 3][lr] = b4.w;
        __syncthreads();

#pragma unroll
        for (int kk = 0; kk < 8; kk++) {
            float ra[8], rb[8];
            *(float4*)&ra[0] = *(const float4*)&As[kk][ty * 8];
            *(float4*)&ra[4] = *(const float4*)&As[kk][ty * 8 + 4];
            *(float4*)&rb[0] = *(const float4*)&Bs[kk][tx * 8];
            *(float4*)&rb[4] = *(const float4*)&Bs[kk][tx * 8 + 4];
#pragma unroll
            for (int i = 0; i < 8; i++)
#pragma unroll
                for (int j = 0; j < 8; j++)
                    acc[i][j] += ra[i] * rb[j];
        }
    }

    float* Cp = C + (size_t)(m0 + ty * 8) * D + n0 + tx * 8;
#pragma unroll
    for (int i = 0; i < 8; i++) {
        *(float4*)(Cp + (size_t)i * D)     = make_float4(acc[i][0], acc[i][1], acc[i][2], acc[i][3]);
        *(float4*)(Cp + (size_t)i * D + 4) = make_float4(acc[i][4], acc[i][5], acc[i][6], acc[i][7]);
    }
}

// ---------------------------------------------------------------------------
// tf32 helpers
// ---------------------------------------------------------------------------
__device__ __forceinline__ unsigned f2tf(float f) {
    unsigned u;
    asm("cvt.rna.tf32.f32 %0, %1;" : "=r"(u) : "f"(f));
    return u;
}

__device__ __forceinline__ void mma_tf32(float c[4],
                                         unsigned a0, unsigned a1, unsigned a2, unsigned a3,
                                         unsigned b0, unsigned b1) {
    asm volatile(
        "mma.sync.aligned.m16n8k8.row.col.f32.tf32.tf32.f32 "
        "{%0,%1,%2,%3}, {%4,%5,%6,%7}, {%8,%9}, {%0,%1,%2,%3};"
        : "+f"(c[0]), "+f"(c[1]), "+f"(c[2]), "+f"(c[3])
        : "r"(a0), "r"(a1), "r"(a2), "r"(a3), "r"(b0), "r"(b1));
}

// ---------------------------------------------------------------------------
// Flash attention with tf32 tensor-core mma.
// grid = (SEQ/64, N_HEADS, BATCH), 128 threads (4 warps x 16 q-rows).
// S tile per warp: 16x64 (8 mma n-tiles). O accum: 16x64.
// K/V smem stride 68 floats -> conflict-free scalar fragment loads.
// ---------------------------------------------------------------------------
__global__ __launch_bounds__(128) void flash_attn_tc(
    const float* __restrict__ Q,
    const float* __restrict__ K,
    const float* __restrict__ V,
    float* __restrict__ O)
{
    __shared__ float Ks[64][68];
    __shared__ float Vs[64][68];

    const int qb   = blockIdx.x;
    const int h    = blockIdx.y;
    const int b    = blockIdx.z;
    const int tid  = threadIdx.x;
    const int warp = tid >> 5;
    const int lane = tid & 31;
    const int g    = lane >> 2;     // groupID (row within 8)
    const int t    = lane & 3;      // thread-in-group
    const int q0   = warp * 16;     // warp's q-row offset in tile

    const size_t base = ((size_t)b * SEQ) * D_MODEL + (size_t)h * HEAD_DIM;

    // ---- preload Q fragments (scaled by 1/8, tf32-rounded) into registers ----
    unsigned qa[8][4];
    {
        const float* Qp = Q + base + (size_t)(qb * 64 + q0) * D_MODEL;
#pragma unroll
        for (int kc = 0; kc < 8; kc++) {
            int c0 = kc * 8 + t;
            qa[kc][0] = f2tf(Qp[(size_t)g       * D_MODEL + c0    ] * 0.125f);
            qa[kc][1] = f2tf(Qp[(size_t)(g + 8) * D_MODEL + c0    ] * 0.125f);
            qa[kc][2] = f2tf(Qp[(size_t)g       * D_MODEL + c0 + 4] * 0.125f);
            qa[kc][3] = f2tf(Qp[(size_t)(g + 8) * D_MODEL + c0 + 4] * 0.125f);
        }
    }

    float o[8][4];
#pragma unroll
    for (int nt = 0; nt < 8; nt++)
#pragma unroll
        for (int j = 0; j < 4; j++) o[nt][j] = 0.f;

    float m0 = -1e30f, m1 = -1e30f, l0 = 0.f, l1 = 0.f;

    for (int kb = 0; kb <= qb; kb++) {
        __syncthreads();   // prior iteration's Vs readers done
        for (int i = tid; i < 64 * 16; i += 128) {
            int row = i >> 4, d = (i & 15) * 4;
            const float* kp = K + base + (size_t)(kb * 64 + row) * D_MODEL + d;
            const float* vp = V + base + (size_t)(kb * 64 + row) * D_MODEL + d;
            float4 kv = *(const float4*)kp;
            float4 vv = *(const float4*)vp;
            float4 kt, vt;
            kt.x = __uint_as_float(f2tf(kv.x)); kt.y = __uint_as_float(f2tf(kv.y));
            kt.z = __uint_as_float(f2tf(kv.z)); kt.w = __uint_as_float(f2tf(kv.w));
            vt.x = __uint_as_float(f2tf(vv.x)); vt.y = __uint_as_float(f2tf(vv.y));
            vt.z = __uint_as_float(f2tf(vv.z)); vt.w = __uint_as_float(f2tf(vv.w));
            *(float4*)&Ks[row][d] = kt;
            *(float4*)&Vs[row][d] = vt;
        }
        __syncthreads();

        // ---- S = Q * K^T ----
        float s[8][4];
#pragma unroll
        for (int nt = 0; nt < 8; nt++)
#pragma unroll
            for (int j = 0; j < 4; j++) s[nt][j] = 0.f;

#pragma unroll
        for (int kc = 0; kc < 8; kc++) {
#pragma unroll
            for (int nt = 0; nt < 8; nt++) {
                unsigned b0 = __float_as_uint(Ks[nt * 8 + g][kc * 8 + t]);
                unsigned b1 = __float_as_uint(Ks[nt * 8 + g][kc * 8 + t + 4]);
                mma_tf32(s[nt], qa[kc][0], qa[kc][1], qa[kc][2], qa[kc][3], b0, b1);
            }
        }

        // ---- causal mask (diagonal block only) ----
        if (kb == qb) {
            int rg0 = qb * 64 + q0 + g;
            int rg1 = rg0 + 8;
#pragma unroll
            for (int nt = 0; nt < 8; nt++) {
                int cg = kb * 64 + nt * 8 + 2 * t;
                if (cg     > rg0) s[nt][0] = -1e30f;
                if (cg + 1 > rg0) s[nt][1] = -1e30f;
                if (cg     > rg1) s[nt][2] = -1e30f;
                if (cg + 1 > rg1) s[nt][3] = -1e30f;
            }
        }

        // ---- online softmax (rows g and g+8; row spread over 4 lanes) ----
        float mn0 = m0, mn1 = m1;
#pragma unroll
        for (int nt = 0; nt < 8; nt++) {
            mn0 = fmaxf(mn0, fmaxf(s[nt][0], s[nt][1]));
            mn1 = fmaxf(mn1, fmaxf(s[nt][2], s[nt][3]));
        }
        mn0 = fmaxf(mn0, __shfl_xor_sync(FULLMASK, mn0, 1));
        mn0 = fmaxf(mn0, __shfl_xor_sync(FULLMASK, mn0, 2));
        mn1 = fmaxf(mn1, __shfl_xor_sync(FULLMASK, mn1, 1));
        mn1 = fmaxf(mn1, __shfl_xor_sync(FULLMASK, mn1, 2));

        float a0s = __expf(m0 - mn0);
        float a1s = __expf(m1 - mn1);
        float ps0 = 0.f, ps1 = 0.f;
#pragma unroll
        for (int nt = 0; nt < 8; nt++) {
            s[nt][0] = __expf(s[nt][0] - mn0);
            s[nt][1] = __expf(s[nt][1] - mn0);
            s[nt][2] = __expf(s[nt][2] - mn1);
            s[nt][3] = __expf(s[nt][3] - mn1);
            ps0 += s[nt][0] + s[nt][1];
            ps1 += s[nt][2] + s[nt][3];
        }
        ps0 += __shfl_xor_sync(FULLMASK, ps0, 1);
        ps0 += __shfl_xor_sync(FULLMASK, ps0, 2);
        ps1 += __shfl_xor_sync(FULLMASK, ps1, 1);
        ps1 += __shfl_xor_sync(FULLMASK, ps1, 2);
        l0 = l0 * a0s + ps0;
        l1 = l1 * a1s + ps1;
        m0 = mn0; m1 = mn1;
#pragma unroll
        for (int nt = 0; nt < 8; nt++) {
            o[nt][0] *= a0s; o[nt][1] *= a0s;
            o[nt][2] *= a1s; o[nt][3] *= a1s;
        }

        // ---- O += P * V ----
        const int src0 = (lane & ~3) | (t >> 1);
        const int src1 = src0 + 2;
#pragma unroll
        for (int kc = 0; kc < 8; kc++) {
            unsigned pu0 = f2tf(s[kc][0]);
            unsigned pu1 = f2tf(s[kc][1]);
            unsigned pu2 = f2tf(s[kc][2]);
            unsigned pu3 = f2tf(s[kc][3]);
            unsigned x00 = __shfl_sync(FULLMASK, pu0, src0);
            unsigned x01 = __shfl_sync(FULLMASK, pu1, src0);
            unsigned x20 = __shfl_sync(FULLMASK, pu2, src0);
            unsigned x21 = __shfl_sync(FULLMASK, pu3, src0);
            unsigned y00 = __shfl_sync(FULLMASK, pu0, src1);
            unsigned y01 = __shfl_sync(FULLMASK, pu1, src1);
            unsigned y20 = __shfl_sync(FULLMASK, pu2, src1);
            unsigned y21 = __shfl_sync(FULLMASK, pu3, src1);
            unsigned a0 = (t & 1) ? x01 : x00;
            unsigned a1 = (t & 1) ? x21 : x20;
            unsigned a2 = (t & 1) ? y01 : y00;
            unsigned a3 = (t & 1) ? y21 : y20;
#pragma unroll
            for (int nt = 0; nt < 8; nt++) {
                unsigned b0 = __float_as_uint(Vs[kc * 8 + t    ][nt * 8 + g]);
                unsigned b1 = __float_as_uint(Vs[kc * 8 + t + 4][nt * 8 + g]);
                mma_tf32(o[nt], a0, a1, a2, a3, b0, b1);
            }
        }
    }

    // ---- normalize + write (float2 per tile per row) ----
    float inv0 = 1.f / l0;
    float inv1 = 1.f / l1;
    float* Op = O + base + (size_t)(qb * 64 + q0) * D_MODEL;
#pragma unroll
    for (int nt = 0; nt < 8; nt++) {
        float2 v0 = make_float2(o[nt][0] * inv0, o[nt][1] * inv0);
        float2 v1 = make_float2(o[nt][2] * inv1, o[nt][3] * inv1);
        *(float2*)(Op + (size_t)g       * D_MODEL + nt * 8 + 2 * t) = v0;
        *(float2*)(Op + (size_t)(g + 8) * D_MODEL + nt * 8 + 2 * t) = v1;
    }
}

// ---------------------------------------------------------------------------
extern "C" void kernel_launch(void* const* d_in, const int* in_sizes, int n_in,
                              void* d_out, int out_size)
{
    const float* x  = (const float*)d_in[0];
    const float* wq = (const float*)d_in[1];
    const float* wk = (const float*)d_in[2];
    const float* wv = (const float*)d_in[3];
    const float* wo = (const float*)d_in[4];
    float* out = (float*)d_out;

    float *q, *k, *v, *ao;
    cudaGetSymbolAddress((void**)&q,  g_q);
    cudaGetSymbolAddress((void**)&k,  g_k);
    cudaGetSymbolAddress((void**)&v,  g_v);
    cudaGetSymbolAddress((void**)&ao, g_ao);

    dim3 gg(D_MODEL / 128, NTOK / 128);   // (8, 32)
    sgemm_nt<<<gg, 256>>>(x, wq, q, NTOK, D_MODEL, D_MODEL);
    sgemm_nt<<<gg, 256>>>(x, wk, k, NTOK, D_MODEL, D_MODEL);
    sgemm_nt<<<gg, 256>>>(x, wv, v, NTOK, D_MODEL, D_MODEL);

    dim3 ga(SEQ / 64, N_HEADS, BATCH);    // (32, 16, 2)
    flash_attn_tc<<<ga, 128>>>(q, k, v, ao);

    sgemm_nt<<<gg, 256>>>(ao, wo, out, NTOK, D_MODEL, D_MODEL);
}

// round 4
// speedup vs baseline: 7.3280x; 3.1527x over previous
#include <cuda_runtime.h>
#include <cuda_bf16.h>

#define D_MODEL  1024
#define N_HEADS  16
#define HEAD_DIM 64
#define BATCH    2
#define SEQ      2048
#define NTOK     (BATCH * SEQ)   // 4096
#define FULLMASK 0xffffffffu

// Scratch (no cudaMalloc allowed)
__device__ float g_q [NTOK * D_MODEL];
__device__ float g_k [NTOK * D_MODEL];
__device__ float g_v [NTOK * D_MODEL];
__device__ float g_ao[NTOK * D_MODEL];

// ---------------------------------------------------------------------------
// tf32 helpers
// ---------------------------------------------------------------------------
__device__ __forceinline__ unsigned f2tf(float f) {
    unsigned u;
    asm("cvt.rna.tf32.f32 %0, %1;" : "=r"(u) : "f"(f));
    return u;
}

__device__ __forceinline__ void mma_tf32(float c[4],
                                         unsigned a0, unsigned a1, unsigned a2, unsigned a3,
                                         unsigned b0, unsigned b1) {
    asm volatile(
        "mma.sync.aligned.m16n8k8.row.col.f32.tf32.tf32.f32 "
        "{%0,%1,%2,%3}, {%4,%5,%6,%7}, {%8,%9}, {%0,%1,%2,%3};"
        : "+f"(c[0]), "+f"(c[1]), "+f"(c[2]), "+f"(c[3])
        : "r"(a0), "r"(a1), "r"(a2), "r"(a3), "r"(b0), "r"(b1));
}

// ---------------------------------------------------------------------------
// tf32 tensor-core GEMM body: C[N,D] = A[N,K] * B[D,K]^T
// 128x128 block tile, BK=16, 256 threads = 8 warps (4 m x 2 n),
// each warp 32x64 (2 x 8 m16n8 tiles). K = D_MODEL = 1024.
// Smem stride 20 floats -> conflict-free scalar fragment loads.
// ---------------------------------------------------------------------------
__device__ __forceinline__ void gemm_tf32_body(
    const float* __restrict__ A,
    const float* __restrict__ B,
    float* __restrict__ C,
    int m0, int n0)
{
    __shared__ float As[128][20];
    __shared__ float Bs[128][20];

    const int tid  = threadIdx.x;
    const int warp = tid >> 5;
    const int lane = tid & 31;
    const int g    = lane >> 2;
    const int t    = lane & 3;
    const int wm   = (warp & 3) * 32;   // warp m offset in tile
    const int wn   = (warp >> 2) * 64;  // warp n offset in tile

    const int lr = tid >> 1;            // 0..127: row for global load
    const int kq = (tid & 1) * 8;       // 0 or 8

    const float* Ap = A + (size_t)(m0 + lr) * D_MODEL + kq;
    const float* Bp = B + (size_t)(n0 + lr) * D_MODEL + kq;

    float acc[2][8][4];
#pragma unroll
    for (int mt = 0; mt < 2; mt++)
#pragma unroll
        for (int nt = 0; nt < 8; nt++)
#pragma unroll
            for (int j = 0; j < 4; j++) acc[mt][nt][j] = 0.f;

    for (int k0 = 0; k0 < D_MODEL; k0 += 16) {
        float4 a0 = *(const float4*)(Ap + k0);
        float4 a1 = *(const float4*)(Ap + k0 + 4);
        float4 b0 = *(const float4*)(Bp + k0);
        float4 b1 = *(const float4*)(Bp + k0 + 4);
        __syncthreads();   // prior iteration's readers done
        {
            float4 ta, tb;
            ta.x = __uint_as_float(f2tf(a0.x)); ta.y = __uint_as_float(f2tf(a0.y));
            ta.z = __uint_as_float(f2tf(a0.z)); ta.w = __uint_as_float(f2tf(a0.w));
            *(float4*)&As[lr][kq] = ta;
            ta.x = __uint_as_float(f2tf(a1.x)); ta.y = __uint_as_float(f2tf(a1.y));
            ta.z = __uint_as_float(f2tf(a1.z)); ta.w = __uint_as_float(f2tf(a1.w));
            *(float4*)&As[lr][kq + 4] = ta;
            tb.x = __uint_as_float(f2tf(b0.x)); tb.y = __uint_as_float(f2tf(b0.y));
            tb.z = __uint_as_float(f2tf(b0.z)); tb.w = __uint_as_float(f2tf(b0.w));
            *(float4*)&Bs[lr][kq] = tb;
            tb.x = __uint_as_float(f2tf(b1.x)); tb.y = __uint_as_float(f2tf(b1.y));
            tb.z = __uint_as_float(f2tf(b1.z)); tb.w = __uint_as_float(f2tf(b1.w));
            *(float4*)&Bs[lr][kq + 4] = tb;
        }
        __syncthreads();

#pragma unroll
        for (int kk = 0; kk < 2; kk++) {
            const int kb = kk * 8;
            unsigned af[2][4];
#pragma unroll
            for (int mt = 0; mt < 2; mt++) {
                af[mt][0] = __float_as_uint(As[wm + mt * 16 + g    ][kb + t    ]);
                af[mt][1] = __float_as_uint(As[wm + mt * 16 + g + 8][kb + t    ]);
                af[mt][2] = __float_as_uint(As[wm + mt * 16 + g    ][kb + t + 4]);
                af[mt][3] = __float_as_uint(As[wm + mt * 16 + g + 8][kb + t + 4]);
            }
            unsigned bf[8][2];
#pragma unroll
            for (int nt = 0; nt < 8; nt++) {
                bf[nt][0] = __float_as_uint(Bs[wn + nt * 8 + g][kb + t    ]);
                bf[nt][1] = __float_as_uint(Bs[wn + nt * 8 + g][kb + t + 4]);
            }
#pragma unroll
            for (int mt = 0; mt < 2; mt++)
#pragma unroll
                for (int nt = 0; nt < 8; nt++)
                    mma_tf32(acc[mt][nt], af[mt][0], af[mt][1], af[mt][2], af[mt][3],
                             bf[nt][0], bf[nt][1]);
        }
    }

    // epilogue
#pragma unroll
    for (int mt = 0; mt < 2; mt++) {
        float* C0 = C + (size_t)(m0 + wm + mt * 16 + g) * D_MODEL + n0 + wn;
        float* C1 = C0 + (size_t)8 * D_MODEL;
#pragma unroll
        for (int nt = 0; nt < 8; nt++) {
            *(float2*)(C0 + nt * 8 + 2 * t) = make_float2(acc[mt][nt][0], acc[mt][nt][1]);
            *(float2*)(C1 + nt * 8 + 2 * t) = make_float2(acc[mt][nt][2], acc[mt][nt][3]);
        }
    }
}

// QKV fused: gridDim = (D_MODEL/128, NTOK/128, 3)
__global__ __launch_bounds__(256) void gemm_qkv_tf32(
    const float* __restrict__ x,
    const float* __restrict__ wq,
    const float* __restrict__ wk,
    const float* __restrict__ wv,
    float* __restrict__ q,
    float* __restrict__ k,
    float* __restrict__ v)
{
    const float* B = (blockIdx.z == 0) ? wq : (blockIdx.z == 1) ? wk : wv;
    float*       C = (blockIdx.z == 0) ? q  : (blockIdx.z == 1) ? k  : v;
    gemm_tf32_body(x, B, C, blockIdx.y * 128, blockIdx.x * 128);
}

// single GEMM: gridDim = (D_MODEL/128, NTOK/128)
__global__ __launch_bounds__(256) void gemm_tf32(
    const float* __restrict__ A,
    const float* __restrict__ B,
    float* __restrict__ C)
{
    gemm_tf32_body(A, B, C, blockIdx.y * 128, blockIdx.x * 128);
}

// ---------------------------------------------------------------------------
// Flash attention with tf32 tensor-core mma (unchanged from R2).
// grid = (SEQ/64, N_HEADS, BATCH), 128 threads (4 warps x 16 q-rows).
// ---------------------------------------------------------------------------
__global__ __launch_bounds__(128) void flash_attn_tc(
    const float* __restrict__ Q,
    const float* __restrict__ K,
    const float* __restrict__ V,
    float* __restrict__ O)
{
    __shared__ float Ks[64][68];
    __shared__ float Vs[64][68];

    const int qb   = blockIdx.x;
    const int h    = blockIdx.y;
    const int b    = blockIdx.z;
    const int tid  = threadIdx.x;
    const int warp = tid >> 5;
    const int lane = tid & 31;
    const int g    = lane >> 2;
    const int t    = lane & 3;
    const int q0   = warp * 16;

    const size_t base = ((size_t)b * SEQ) * D_MODEL + (size_t)h * HEAD_DIM;

    unsigned qa[8][4];
    {
        const float* Qp = Q + base + (size_t)(qb * 64 + q0) * D_MODEL;
#pragma unroll
        for (int kc = 0; kc < 8; kc++) {
            int c0 = kc * 8 + t;
            qa[kc][0] = f2tf(Qp[(size_t)g       * D_MODEL + c0    ] * 0.125f);
            qa[kc][1] = f2tf(Qp[(size_t)(g + 8) * D_MODEL + c0    ] * 0.125f);
            qa[kc][2] = f2tf(Qp[(size_t)g       * D_MODEL + c0 + 4] * 0.125f);
            qa[kc][3] = f2tf(Qp[(size_t)(g + 8) * D_MODEL + c0 + 4] * 0.125f);
        }
    }

    float o[8][4];
#pragma unroll
    for (int nt = 0; nt < 8; nt++)
#pragma unroll
        for (int j = 0; j < 4; j++) o[nt][j] = 0.f;

    float m0 = -1e30f, m1 = -1e30f, l0 = 0.f, l1 = 0.f;

    for (int kb = 0; kb <= qb; kb++) {
        __syncthreads();
        for (int i = tid; i < 64 * 16; i += 128) {
            int row = i >> 4, d = (i & 15) * 4;
            const float* kp = K + base + (size_t)(kb * 64 + row) * D_MODEL + d;
            const float* vp = V + base + (size_t)(kb * 64 + row) * D_MODEL + d;
            float4 kv = *(const float4*)kp;
            float4 vv = *(const float4*)vp;
            float4 kt, vt;
            kt.x = __uint_as_float(f2tf(kv.x)); kt.y = __uint_as_float(f2tf(kv.y));
            kt.z = __uint_as_float(f2tf(kv.z)); kt.w = __uint_as_float(f2tf(kv.w));
            vt.x = __uint_as_float(f2tf(vv.x)); vt.y = __uint_as_float(f2tf(vv.y));
            vt.z = __uint_as_float(f2tf(vv.z)); vt.w = __uint_as_float(f2tf(vv.w));
            *(float4*)&Ks[row][d] = kt;
            *(float4*)&Vs[row][d] = vt;
        }
        __syncthreads();

        float s[8][4];
#pragma unroll
        for (int nt = 0; nt < 8; nt++)
#pragma unroll
            for (int j = 0; j < 4; j++) s[nt][j] = 0.f;

#pragma unroll
        for (int kc = 0; kc < 8; kc++) {
#pragma unroll
            for (int nt = 0; nt < 8; nt++) {
                unsigned b0 = __float_as_uint(Ks[nt * 8 + g][kc * 8 + t]);
                unsigned b1 = __float_as_uint(Ks[nt * 8 + g][kc * 8 + t + 4]);
                mma_tf32(s[nt], qa[kc][0], qa[kc][1], qa[kc][2], qa[kc][3], b0, b1);
            }
        }

        if (kb == qb) {
            int rg0 = qb * 64 + q0 + g;
            int rg1 = rg0 + 8;
#pragma unroll
            for (int nt = 0; nt < 8; nt++) {
                int cg = kb * 64 + nt * 8 + 2 * t;
                if (cg     > rg0) s[nt][0] = -1e30f;
                if (cg + 1 > rg0) s[nt][1] = -1e30f;
                if (cg     > rg1) s[nt][2] = -1e30f;
                if (cg + 1 > rg1) s[nt][3] = -1e30f;
            }
        }

        float mn0 = m0, mn1 = m1;
#pragma unroll
        for (int nt = 0; nt < 8; nt++) {
            mn0 = fmaxf(mn0, fmaxf(s[nt][0], s[nt][1]));
            mn1 = fmaxf(mn1, fmaxf(s[nt][2], s[nt][3]));
        }
        mn0 = fmaxf(mn0, __shfl_xor_sync(FULLMASK, mn0, 1));
        mn0 = fmaxf(mn0, __shfl_xor_sync(FULLMASK, mn0, 2));
        mn1 = fmaxf(mn1, __shfl_xor_sync(FULLMASK, mn1, 1));
        mn1 = fmaxf(mn1, __shfl_xor_sync(FULLMASK, mn1, 2));

        float a0s = __expf(m0 - mn0);
        float a1s = __expf(m1 - mn1);
        float ps0 = 0.f, ps1 = 0.f;
#pragma unroll
        for (int nt = 0; nt < 8; nt++) {
            s[nt][0] = __expf(s[nt][0] - mn0);
            s[nt][1] = __expf(s[nt][1] - mn0);
            s[nt][2] = __expf(s[nt][2] - mn1);
            s[nt][3] = __expf(s[nt][3] - mn1);
            ps0 += s[nt][0] + s[nt][1];
            ps1 += s[nt][2] + s[nt][3];
        }
        ps0 += __shfl_xor_sync(FULLMASK, ps0, 1);
        ps0 += __shfl_xor_sync(FULLMASK, ps0, 2);
        ps1 += __shfl_xor_sync(FULLMASK, ps1, 1);
        ps1 += __shfl_xor_sync(FULLMASK, ps1, 2);
        l0 = l0 * a0s + ps0;
        l1 = l1 * a1s + ps1;
        m0 = mn0; m1 = mn1;
#pragma unroll
        for (int nt = 0; nt < 8; nt++) {
            o[nt][0] *= a0s; o[nt][1] *= a0s;
            o[nt][2] *= a1s; o[nt][3] *= a1s;
        }

        const int src0 = (lane & ~3) | (t >> 1);
        const int src1 = src0 + 2;
#pragma unroll
        for (int kc = 0; kc < 8; kc++) {
            unsigned pu0 = f2tf(s[kc][0]);
            unsigned pu1 = f2tf(s[kc][1]);
            unsigned pu2 = f2tf(s[kc][2]);
            unsigned pu3 = f2tf(s[kc][3]);
            unsigned x00 = __shfl_sync(FULLMASK, pu0, src0);
            unsigned x01 = __shfl_sync(FULLMASK, pu1, src0);
            unsigned x20 = __shfl_sync(FULLMASK, pu2, src0);
            unsigned x21 = __shfl_sync(FULLMASK, pu3, src0);
            unsigned y00 = __shfl_sync(FULLMASK, pu0, src1);
            unsigned y01 = __shfl_sync(FULLMASK, pu1, src1);
            unsigned y20 = __shfl_sync(FULLMASK, pu2, src1);
            unsigned y21 = __shfl_sync(FULLMASK, pu3, src1);
            unsigned a0 = (t & 1) ? x01 : x00;
            unsigned a1 = (t & 1) ? x21 : x20;
            unsigned a2 = (t & 1) ? y01 : y00;
            unsigned a3 = (t & 1) ? y21 : y20;
#pragma unroll
            for (int nt = 0; nt < 8; nt++) {
                unsigned b0 = __float_as_uint(Vs[kc * 8 + t    ][nt * 8 + g]);
                unsigned b1 = __float_as_uint(Vs[kc * 8 + t + 4][nt * 8 + g]);
                mma_tf32(o[nt], a0, a1, a2, a3, b0, b1);
            }
        }
    }

    float inv0 = 1.f / l0;
    float inv1 = 1.f / l1;
    float* Op = O + base + (size_t)(qb * 64 + q0) * D_MODEL;
#pragma unroll
    for (int nt = 0; nt < 8; nt++) {
        float2 v0 = make_float2(o[nt][0] * inv0, o[nt][1] * inv0);
        float2 v1 = make_float2(o[nt][2] * inv1, o[nt][3] * inv1);
        *(float2*)(Op + (size_t)g       * D_MODEL + nt * 8 + 2 * t) = v0;
        *(float2*)(Op + (size_t)(g + 8) * D_MODEL + nt * 8 + 2 * t) = v1;
    }
}

// ---------------------------------------------------------------------------
extern "C" void kernel_launch(void* const* d_in, const int* in_sizes, int n_in,
                              void* d_out, int out_size)
{
    const float* x  = (const float*)d_in[0];
    const float* wq = (const float*)d_in[1];
    const float* wk = (const float*)d_in[2];
    const float* wv = (const float*)d_in[3];
    const float* wo = (const float*)d_in[4];
    float* out = (float*)d_out;

    float *q, *k, *v, *ao;
    cudaGetSymbolAddress((void**)&q,  g_q);
    cudaGetSymbolAddress((void**)&k,  g_k);
    cudaGetSymbolAddress((void**)&v,  g_v);
    cudaGetSymbolAddress((void**)&ao, g_ao);

    dim3 gqkv(D_MODEL / 128, NTOK / 128, 3);   // (8, 32, 3)
    gemm_qkv_tf32<<<gqkv, 256>>>(x, wq, wk, wv, q, k, v);

    dim3 ga(SEQ / 64, N_HEADS, BATCH);         // (32, 16, 2)
    flash_attn_tc<<<ga, 128>>>(q, k, v, ao);

    dim3 go(D_MODEL / 128, NTOK / 128);        // (8, 32)
    gemm_tf32<<<go, 256>>>(ao, wo, out);
}

// round 5
// speedup vs baseline: 7.4953x; 1.0228x over previous
#include <cuda_runtime.h>
#include <cuda_bf16.h>

#define D_MODEL  1024
#define N_HEADS  16
#define HEAD_DIM 64
#define BATCH    2
#define SEQ      2048
#define NTOK     (BATCH * SEQ)   // 4096
#define FULLMASK 0xffffffffu

// Scratch (no cudaMalloc allowed)
__device__ float g_q [NTOK * D_MODEL];
__device__ float g_k [NTOK * D_MODEL];
__device__ float g_v [NTOK * D_MODEL];
__device__ float g_ao[NTOK * D_MODEL];

// ---------------------------------------------------------------------------
// helpers
// ---------------------------------------------------------------------------
__device__ __forceinline__ unsigned f2tf(float f) {
    unsigned u;
    asm("cvt.rna.tf32.f32 %0, %1;" : "=r"(u) : "f"(f));
    return u;
}

__device__ __forceinline__ void mma_tf32(float c[4],
                                         unsigned a0, unsigned a1, unsigned a2, unsigned a3,
                                         unsigned b0, unsigned b1) {
    asm volatile(
        "mma.sync.aligned.m16n8k8.row.col.f32.tf32.tf32.f32 "
        "{%0,%1,%2,%3}, {%4,%5,%6,%7}, {%8,%9}, {%0,%1,%2,%3};"
        : "+f"(c[0]), "+f"(c[1]), "+f"(c[2]), "+f"(c[3])
        : "r"(a0), "r"(a1), "r"(a2), "r"(a3), "r"(b0), "r"(b1));
}

__device__ __forceinline__ void ldsm4(unsigned& r0, unsigned& r1, unsigned& r2, unsigned& r3,
                                      const void* p) {
    unsigned addr = (unsigned)__cvta_generic_to_shared(p);
    asm volatile("ldmatrix.sync.aligned.m8n8.x4.shared.b16 {%0,%1,%2,%3}, [%4];"
                 : "=r"(r0), "=r"(r1), "=r"(r2), "=r"(r3) : "r"(addr));
}

__device__ __forceinline__ float tfr(float f) { return __uint_as_float(f2tf(f)); }

// ---------------------------------------------------------------------------
// tf32 GEMM: C[N,D] = A[N,K] * B[D,K]^T, 128x128 tile, BK=16, 256 thr, 8 warps.
// ldmatrix fragment loads, stride-20 smem (conflict-free for LDSM row sets),
// register-prefetched global loads.
// ---------------------------------------------------------------------------
__device__ __forceinline__ void gemm_tf32_body(
    const float* __restrict__ A,
    const float* __restrict__ B,
    float* __restrict__ C,
    int m0, int n0)
{
    __shared__ float As[128][20];
    __shared__ float Bs[128][20];

    const int tid  = threadIdx.x;
    const int warp = tid >> 5;
    const int lane = tid & 31;
    const int g    = lane >> 2;
    const int t    = lane & 3;
    const int wm   = (warp & 3) * 32;
    const int wn   = (warp >> 2) * 64;

    const int lr = tid >> 1;
    const int kq = (tid & 1) * 8;

    const float* Ap = A + (size_t)(m0 + lr) * D_MODEL + kq;
    const float* Bp = B + (size_t)(n0 + lr) * D_MODEL + kq;

    // ldmatrix source addresses (kb=0 base; +kb floats per kk step)
    const float* aAddr[2];
#pragma unroll
    for (int mt = 0; mt < 2; mt++)
        aAddr[mt] = &As[wm + mt * 16 + (lane & 15)][(lane >> 4) * 4];
    const float* bAddr[4];
#pragma unroll
    for (int ntp = 0; ntp < 4; ntp++)
        bAddr[ntp] = &Bs[wn + ntp * 16 + ((lane >> 4) << 3) + (lane & 7)][((lane >> 3) & 1) * 4];

    float acc[2][8][4];
#pragma unroll
    for (int mt = 0; mt < 2; mt++)
#pragma unroll
        for (int nt = 0; nt < 8; nt++)
#pragma unroll
            for (int j = 0; j < 4; j++) acc[mt][nt][j] = 0.f;

    float4 pa0 = *(const float4*)(Ap);
    float4 pa1 = *(const float4*)(Ap + 4);
    float4 pb0 = *(const float4*)(Bp);
    float4 pb1 = *(const float4*)(Bp + 4);

    for (int k0 = 0; k0 < D_MODEL; k0 += 16) {
        __syncthreads();   // prior readers done
        *(float4*)&As[lr][kq]     = make_float4(tfr(pa0.x), tfr(pa0.y), tfr(pa0.z), tfr(pa0.w));
        *(float4*)&As[lr][kq + 4] = make_float4(tfr(pa1.x), tfr(pa1.y), tfr(pa1.z), tfr(pa1.w));
        *(float4*)&Bs[lr][kq]     = make_float4(tfr(pb0.x), tfr(pb0.y), tfr(pb0.z), tfr(pb0.w));
        *(float4*)&Bs[lr][kq + 4] = make_float4(tfr(pb1.x), tfr(pb1.y), tfr(pb1.z), tfr(pb1.w));
        __syncthreads();

        if (k0 + 16 < D_MODEL) {    // prefetch next tile
            pa0 = *(const float4*)(Ap + k0 + 16);
            pa1 = *(const float4*)(Ap + k0 + 20);
            pb0 = *(const float4*)(Bp + k0 + 16);
            pb1 = *(const float4*)(Bp + k0 + 20);
        }

#pragma unroll
        for (int kk = 0; kk < 2; kk++) {
            const int kb = kk * 8;
            unsigned af[2][4];
#pragma unroll
            for (int mt = 0; mt < 2; mt++)
                ldsm4(af[mt][0], af[mt][1], af[mt][2], af[mt][3], aAddr[mt] + kb);
            unsigned bf[8][2];
#pragma unroll
            for (int ntp = 0; ntp < 4; ntp++)
                ldsm4(bf[ntp * 2][0], bf[ntp * 2][1], bf[ntp * 2 + 1][0], bf[ntp * 2 + 1][1],
                      bAddr[ntp] + kb);
#pragma unroll
            for (int mt = 0; mt < 2; mt++)
#pragma unroll
                for (int nt = 0; nt < 8; nt++)
                    mma_tf32(acc[mt][nt], af[mt][0], af[mt][1], af[mt][2], af[mt][3],
                             bf[nt][0], bf[nt][1]);
        }
    }

#pragma unroll
    for (int mt = 0; mt < 2; mt++) {
        float* C0 = C + (size_t)(m0 + wm + mt * 16 + g) * D_MODEL + n0 + wn;
        float* C1 = C0 + (size_t)8 * D_MODEL;
#pragma unroll
        for (int nt = 0; nt < 8; nt++) {
            *(float2*)(C0 + nt * 8 + 2 * t) = make_float2(acc[mt][nt][0], acc[mt][nt][1]);
            *(float2*)(C1 + nt * 8 + 2 * t) = make_float2(acc[mt][nt][2], acc[mt][nt][3]);
        }
    }
}

__global__ __launch_bounds__(256) void gemm_qkv_tf32(
    const float* __restrict__ x,
    const float* __restrict__ wq,
    const float* __restrict__ wk,
    const float* __restrict__ wv,
    float* __restrict__ q,
    float* __restrict__ k,
    float* __restrict__ v)
{
    const float* B = (blockIdx.z == 0) ? wq : (blockIdx.z == 1) ? wk : wv;
    float*       C = (blockIdx.z == 0) ? q  : (blockIdx.z == 1) ? k  : v;
    gemm_tf32_body(x, B, C, blockIdx.y * 128, blockIdx.x * 128);
}

__global__ __launch_bounds__(256) void gemm_tf32(
    const float* __restrict__ A,
    const float* __restrict__ B,
    float* __restrict__ C)
{
    gemm_tf32_body(A, B, C, blockIdx.y * 128, blockIdx.x * 128);
}

// ---------------------------------------------------------------------------
// Flash attention, tf32 mma + ldmatrix.
// grid = (SEQ/128, N_HEADS, BATCH), 256 threads = 8 warps x 16 q-rows.
// K stored [k][d] (stride 68), V stored transposed [d][k] (stride 68);
// both fragment-loaded via ldmatrix. Global K/V register-prefetched.
// ---------------------------------------------------------------------------
__global__ __launch_bounds__(256) void flash_attn_tc(
    const float* __restrict__ Q,
    const float* __restrict__ K,
    const float* __restrict__ V,
    float* __restrict__ O)
{
    __shared__ float Ks[64][68];
    __shared__ float Vt[64][68];   // [d][k]

    const int qb   = gridDim.x - 1 - blockIdx.x;   // big tiles first
    const int h    = blockIdx.y;
    const int b    = blockIdx.z;
    const int tid  = threadIdx.x;
    const int warp = tid >> 5;
    const int lane = tid & 31;
    const int g    = lane >> 2;
    const int t    = lane & 3;
    const int q0   = warp * 16;                    // warp q-row offset in 128-row tile

    const size_t base = ((size_t)b * SEQ) * D_MODEL + (size_t)h * HEAD_DIM;

    // ldmatrix source addresses for K (QK b-frags) and Vt (PV b-frags)
    const int frow = ((lane >> 4) << 3) + (lane & 7);
    const int fcol = ((lane >> 3) & 1) * 4;
    const float* kAddr[4];
    const float* vAddr[4];
#pragma unroll
    for (int ntp = 0; ntp < 4; ntp++) {
        kAddr[ntp] = &Ks[ntp * 16 + frow][fcol];
        vAddr[ntp] = &Vt[ntp * 16 + frow][fcol];
    }

    // preload Q fragments (scaled, tf32)
    unsigned qa[8][4];
    {
        const float* Qp = Q + base + (size_t)(qb * 128 + q0) * D_MODEL;
#pragma unroll
        for (int kc = 0; kc < 8; kc++) {
            int c0 = kc * 8 + t;
            qa[kc][0] = f2tf(Qp[(size_t)g       * D_MODEL + c0    ] * 0.125f);
            qa[kc][1] = f2tf(Qp[(size_t)(g + 8) * D_MODEL + c0    ] * 0.125f);
            qa[kc][2] = f2tf(Qp[(size_t)g       * D_MODEL + c0 + 4] * 0.125f);
            qa[kc][3] = f2tf(Qp[(size_t)(g + 8) * D_MODEL + c0 + 4] * 0.125f);
        }
    }

    float o[8][4];
#pragma unroll
    for (int nt = 0; nt < 8; nt++)
#pragma unroll
        for (int j = 0; j < 4; j++) o[nt][j] = 0.f;

    float m0 = -1e30f, m1 = -1e30f, l0 = 0.f, l1 = 0.f;

    const int kbmax = 2 * qb + 1;
    const int warp_max_row = qb * 128 + q0 + 15;

    // prefetch tile kb=0 (4 float4 K + 4 float4 V per thread)
    float4 kreg[4], vreg[4];
#pragma unroll
    for (int j = 0; j < 4; j++) {
        int i = tid + j * 256;
        int row = i >> 4, d = (i & 15) * 4;
        kreg[j] = *(const float4*)(K + base + (size_t)row * D_MODEL + d);
        vreg[j] = *(const float4*)(V + base + (size_t)row * D_MODEL + d);
    }

    for (int kb = 0; kb <= kbmax; kb++) {
        __syncthreads();   // prior readers done
#pragma unroll
        for (int j = 0; j < 4; j++) {
            int i = tid + j * 256;
            int row = i >> 4, d = (i & 15) * 4;
            *(float4*)&Ks[row][d] = make_float4(tfr(kreg[j].x), tfr(kreg[j].y),
                                                tfr(kreg[j].z), tfr(kreg[j].w));
            Vt[d    ][row] = tfr(vreg[j].x);
            Vt[d + 1][row] = tfr(vreg[j].y);
            Vt[d + 2][row] = tfr(vreg[j].z);
            Vt[d + 3][row] = tfr(vreg[j].w);
        }
        __syncthreads();

        if (kb < kbmax) {   // prefetch next tile
#pragma unroll
            for (int j = 0; j < 4; j++) {
                int i = tid + j * 256;
                int row = (kb + 1) * 64 + (i >> 4);
                int d = (i & 15) * 4;
                kreg[j] = *(const float4*)(K + base + (size_t)row * D_MODEL + d);
                vreg[j] = *(const float4*)(V + base + (size_t)row * D_MODEL + d);
            }
        }

        if (kb * 64 > warp_max_row) continue;   // warp fully masked

        // ---- S = Q K^T ----
        float s[8][4];
#pragma unroll
        for (int nt = 0; nt < 8; nt++)
#pragma unroll
            for (int j = 0; j < 4; j++) s[nt][j] = 0.f;

#pragma unroll
        for (int kc = 0; kc < 8; kc++) {
            unsigned bf[8][2];
#pragma unroll
            for (int ntp = 0; ntp < 4; ntp++)
                ldsm4(bf[ntp * 2][0], bf[ntp * 2][1], bf[ntp * 2 + 1][0], bf[ntp * 2 + 1][1],
                      kAddr[ntp] + kc * 8);
#pragma unroll
            for (int nt = 0; nt < 8; nt++)
                mma_tf32(s[nt], qa[kc][0], qa[kc][1], qa[kc][2], qa[kc][3],
                         bf[nt][0], bf[nt][1]);
        }

        // ---- causal mask (diagonal region) ----
        if (kb >= 2 * qb) {
            int rg0 = qb * 128 + q0 + g;
            int rg1 = rg0 + 8;
#pragma unroll
            for (int nt = 0; nt < 8; nt++) {
                int cg = kb * 64 + nt * 8 + 2 * t;
                if (cg     > rg0) s[nt][0] = -1e30f;
                if (cg + 1 > rg0) s[nt][1] = -1e30f;
                if (cg     > rg1) s[nt][2] = -1e30f;
                if (cg + 1 > rg1) s[nt][3] = -1e30f;
            }
        }

        // ---- online softmax ----
        float mn0 = m0, mn1 = m1;
#pragma unroll
        for (int nt = 0; nt < 8; nt++) {
            mn0 = fmaxf(mn0, fmaxf(s[nt][0], s[nt][1]));
            mn1 = fmaxf(mn1, fmaxf(s[nt][2], s[nt][3]));
        }
        mn0 = fmaxf(mn0, __shfl_xor_sync(FULLMASK, mn0, 1));
        mn0 = fmaxf(mn0, __shfl_xor_sync(FULLMASK, mn0, 2));
        mn1 = fmaxf(mn1, __shfl_xor_sync(FULLMASK, mn1, 1));
        mn1 = fmaxf(mn1, __shfl_xor_sync(FULLMASK, mn1, 2));

        float a0s = __expf(m0 - mn0);
        float a1s = __expf(m1 - mn1);
        float ps0 = 0.f, ps1 = 0.f;
#pragma unroll
        for (int nt = 0; nt < 8; nt++) {
            s[nt][0] = __expf(s[nt][0] - mn0);
            s[nt][1] = __expf(s[nt][1] - mn0);
            s[nt][2] = __expf(s[nt][2] - mn1);
            s[nt][3] = __expf(s[nt][3] - mn1);
            ps0 += s[nt][0] + s[nt][1];
            ps1 += s[nt][2] + s[nt][3];
        }
        ps0 += __shfl_xor_sync(FULLMASK, ps0, 1);
        ps0 += __shfl_xor_sync(FULLMASK, ps0, 2);
        ps1 += __shfl_xor_sync(FULLMASK, ps1, 1);
        ps1 += __shfl_xor_sync(FULLMASK, ps1, 2);
        l0 = l0 * a0s + ps0;
        l1 = l1 * a1s + ps1;
        m0 = mn0; m1 = mn1;
#pragma unroll
        for (int nt = 0; nt < 8; nt++) {
            o[nt][0] *= a0s; o[nt][1] *= a0s;
            o[nt][2] *= a1s; o[nt][3] *= a1s;
        }

        // ---- O += P V ----
        const int src0 = (lane & ~3) | (t >> 1);
        const int src1 = src0 + 2;
#pragma unroll
        for (int kc = 0; kc < 8; kc++) {
            unsigned pu0 = f2tf(s[kc][0]);
            unsigned pu1 = f2tf(s[kc][1]);
            unsigned pu2 = f2tf(s[kc][2]);
            unsigned pu3 = f2tf(s[kc][3]);
            unsigned x00 = __shfl_sync(FULLMASK, pu0, src0);
            unsigned x01 = __shfl_sync(FULLMASK, pu1, src0);
            unsigned x20 = __shfl_sync(FULLMASK, pu2, src0);
            unsigned x21 = __shfl_sync(FULLMASK, pu3, src0);
            unsigned y00 = __shfl_sync(FULLMASK, pu0, src1);
            unsigned y01 = __shfl_sync(FULLMASK, pu1, src1);
            unsigned y20 = __shfl_sync(FULLMASK, pu2, src1);
            unsigned y21 = __shfl_sync(FULLMASK, pu3, src1);
            unsigned a0 = (t & 1) ? x01 : x00;
            unsigned a1 = (t & 1) ? x21 : x20;
            unsigned a2 = (t & 1) ? y01 : y00;
            unsigned a3 = (t & 1) ? y21 : y20;
            unsigned bf[8][2];
#pragma unroll
            for (int ntp = 0; ntp < 4; ntp++)
                ldsm4(bf[ntp * 2][0], bf[ntp * 2][1], bf[ntp * 2 + 1][0], bf[ntp * 2 + 1][1],
                      vAddr[ntp] + kc * 8);
#pragma unroll
            for (int nt = 0; nt < 8; nt++)
                mma_tf32(o[nt], a0, a1, a2, a3, bf[nt][0], bf[nt][1]);
        }
    }

    // ---- normalize + write ----
    float inv0 = 1.f / l0;
    float inv1 = 1.f / l1;
    float* Op = O + base + (size_t)(qb * 128 + q0) * D_MODEL;
#pragma unroll
    for (int nt = 0; nt < 8; nt++) {
        *(float2*)(Op + (size_t)g       * D_MODEL + nt * 8 + 2 * t) =
            make_float2(o[nt][0] * inv0, o[nt][1] * inv0);
        *(float2*)(Op + (size_t)(g + 8) * D_MODEL + nt * 8 + 2 * t) =
            make_float2(o[nt][2] * inv1, o[nt][3] * inv1);
    }
}

// ---------------------------------------------------------------------------
extern "C" void kernel_launch(void* const* d_in, const int* in_sizes, int n_in,
                              void* d_out, int out_size)
{
    const float* x  = (const float*)d_in[0];
    const float* wq = (const float*)d_in[1];
    const float* wk = (const float*)d_in[2];
    const float* wv = (const float*)d_in[3];
    const float* wo = (const float*)d_in[4];
    float* out = (float*)d_out;

    float *q, *k, *v, *ao;
    cudaGetSymbolAddress((void**)&q,  g_q);
    cudaGetSymbolAddress((void**)&k,  g_k);
    cudaGetSymbolAddress((void**)&v,  g_v);
    cudaGetSymbolAddress((void**)&ao, g_ao);

    dim3 gqkv(D_MODEL / 128, NTOK / 128, 3);   // (8, 32, 3)
    gemm_qkv_tf32<<<gqkv, 256>>>(x, wq, wk, wv, q, k, v);

    dim3 ga(SEQ / 128, N_HEADS, BATCH);        // (16, 16, 2)
    flash_attn_tc<<<ga, 256>>>(q, k, v, ao);

    dim3 go(D_MODEL / 128, NTOK / 128);        // (8, 32)
    gemm_tf32<<<go, 256>>>(ao, wo, out);
}

// round 7
// speedup vs baseline: 10.5928x; 1.4133x over previous
#include <cuda_runtime.h>
#include <cuda_fp16.h>
#include <cstdint>

#define D_MODEL  1024
#define N_HEADS  16
#define HEAD_DIM 64
#define BATCH    2
#define SEQ      2048
#define NTOK     (BATCH * SEQ)   // 4096
#define FULLMASK 0xffffffffu

// Scratch (no cudaMalloc allowed)
__device__ float g_q [NTOK * D_MODEL];
__device__ float g_k [NTOK * D_MODEL];
__device__ float g_v [NTOK * D_MODEL];
__device__ float g_ao[NTOK * D_MODEL];

// ---------------------------------------------------------------------------
// helpers
// ---------------------------------------------------------------------------
__device__ __forceinline__ uint32_t smem_u32(const void* p) {
    return (uint32_t)__cvta_generic_to_shared(p);
}

__device__ __forceinline__ unsigned f22u(float a, float b) {
    __half2 h = __floats2half2_rn(a, b);
    return *reinterpret_cast<unsigned*>(&h);
}

__device__ __forceinline__ void mma_f16(float c[4],
                                        unsigned a0, unsigned a1, unsigned a2, unsigned a3,
                                        unsigned b0, unsigned b1) {
    asm volatile(
        "mma.sync.aligned.m16n8k16.row.col.f32.f16.f16.f32 "
        "{%0,%1,%2,%3}, {%4,%5,%6,%7}, {%8,%9}, {%0,%1,%2,%3};"
        : "+f"(c[0]), "+f"(c[1]), "+f"(c[2]), "+f"(c[3])
        : "r"(a0), "r"(a1), "r"(a2), "r"(a3), "r"(b0), "r"(b1));
}

__device__ __forceinline__ void ldsm4(unsigned& r0, unsigned& r1, unsigned& r2, unsigned& r3,
                                      uint32_t addr) {
    asm volatile("ldmatrix.sync.aligned.m8n8.x4.shared.b16 {%0,%1,%2,%3}, [%4];"
                 : "=r"(r0), "=r"(r1), "=r"(r2), "=r"(r3) : "r"(addr));
}

__device__ __forceinline__ void sts16(uint32_t addr, unsigned r0, unsigned r1,
                                      unsigned r2, unsigned r3) {
    asm volatile("st.shared.v4.b32 [%0], {%1,%2,%3,%4};"
                 :: "r"(addr), "r"(r0), "r"(r1), "r"(r2), "r"(r3) : "memory");
}

// ---------------------------------------------------------------------------
// fp16 GEMM: C[N,D] = A[N,K] * B[D,K]^T.  128x128 tile, 256 thr, 8 warps
// (4m x 2n), warp tile 32x64 = 2x8 m16n8k16 tiles. K staged 32 at a time,
// 2-stage smem double buffer, one __syncthreads per stage.
// Smem stride 40 halves (80B): 8-row ldmatrix phases hit disjoint bank groups.
// ---------------------------------------------------------------------------
#define GSTR 40

__device__ __forceinline__ void gemm_f16_body(
    const float* __restrict__ A,
    const float* __restrict__ B,
    float* __restrict__ C,
    int m0, int n0)
{
    __shared__ __half As[2][128][GSTR];
    __shared__ __half Bs[2][128][GSTR];

    const int tid  = threadIdx.x;
    const int warp = tid >> 5;
    const int lane = tid & 31;
    const int g    = lane >> 2;
    const int t    = lane & 3;
    const int wm   = (warp & 3) * 32;
    const int wn   = (warp >> 2) * 64;

    const int row = tid >> 1;
    const int hb  = (tid & 1) * 16;      // half-offset within 32-wide stage

    const float* Ap = A + (size_t)(m0 + row) * D_MODEL + hb;
    const float* Bp = B + (size_t)(n0 + row) * D_MODEL + hb;

    const uint32_t dstA = smem_u32(&As[0][row][hb]);
    const uint32_t dstB = smem_u32(&Bs[0][row][hb]);
    const uint32_t BUFB = 128u * GSTR * 2u;   // bytes per buffer

    uint32_t aAd[2];
#pragma unroll
    for (int mt = 0; mt < 2; mt++)
        aAd[mt] = smem_u32(&As[0][wm + mt * 16 + (lane & 15)][(lane >> 4) * 8]);
    const int frow = (lane & 7) + ((lane >> 4) << 3);
    const int fch  = ((lane >> 3) & 1) * 8;
    uint32_t bAd[4];
#pragma unroll
    for (int np = 0; np < 4; np++)
        bAd[np] = smem_u32(&Bs[0][wn + np * 16 + frow][fch]);

    float acc[2][8][4] = {};

    float4 pa[4], pb[4];
#pragma unroll
    for (int j = 0; j < 4; j++) {
        pa[j] = *(const float4*)(Ap + j * 4);
        pb[j] = *(const float4*)(Bp + j * 4);
    }
#pragma unroll
    for (int j = 0; j < 2; j++) {
        sts16(dstA + j * 16,
              f22u(pa[2*j].x, pa[2*j].y), f22u(pa[2*j].z, pa[2*j].w),
              f22u(pa[2*j+1].x, pa[2*j+1].y), f22u(pa[2*j+1].z, pa[2*j+1].w));
        sts16(dstB + j * 16,
              f22u(pb[2*j].x, pb[2*j].y), f22u(pb[2*j].z, pb[2*j].w),
              f22u(pb[2*j+1].x, pb[2*j+1].y), f22u(pb[2*j+1].z, pb[2*j+1].w));
    }
    __syncthreads();

    for (int s = 0; s < 32; s++) {
        const uint32_t off = (uint32_t)(s & 1) * BUFB;
        if (s + 1 < 32) {
#pragma unroll
            for (int j = 0; j < 4; j++) {
                pa[j] = *(const float4*)(Ap + (s + 1) * 32 + j * 4);
                pb[j] = *(const float4*)(Bp + (s + 1) * 32 + j * 4);
            }
        }
#pragma unroll
        for (int kc = 0; kc < 2; kc++) {
            const uint32_t ko = off + kc * 32;   // 16 halves
            unsigned af[2][4];
#pragma unroll
            for (int mt = 0; mt < 2; mt++)
                ldsm4(af[mt][0], af[mt][1], af[mt][2], af[mt][3], aAd[mt] + ko);
            unsigned bf[8][2];
#pragma unroll
            for (int np = 0; np < 4; np++)
                ldsm4(bf[np*2][0], bf[np*2][1], bf[np*2+1][0], bf[np*2+1][1],
                      bAd[np] + ko);
#pragma unroll
            for (int mt = 0; mt < 2; mt++)
#pragma unroll
                for (int nt = 0; nt < 8; nt++)
                    mma_f16(acc[mt][nt], af[mt][0], af[mt][1], af[mt][2], af[mt][3],
                            bf[nt][0], bf[nt][1]);
        }
        if (s + 1 < 32) {
            const uint32_t wo = (uint32_t)((s + 1) & 1) * BUFB;
#pragma unroll
            for (int j = 0; j < 2; j++) {
                sts16(dstA + wo + j * 16,
                      f22u(pa[2*j].x, pa[2*j].y), f22u(pa[2*j].z, pa[2*j].w),
                      f22u(pa[2*j+1].x, pa[2*j+1].y), f22u(pa[2*j+1].z, pa[2*j+1].w));
                sts16(dstB + wo + j * 16,
                      f22u(pb[2*j].x, pb[2*j].y), f22u(pb[2*j].z, pb[2*j].w),
                      f22u(pb[2*j+1].x, pb[2*j+1].y), f22u(pb[2*j+1].z, pb[2*j+1].w));
            }
        }
        __syncthreads();
    }

#pragma unroll
    for (int mt = 0; mt < 2; mt++) {
        float* C0 = C + (size_t)(m0 + wm + mt * 16 + g) * D_MODEL + n0 + wn;
        float* C1 = C0 + (size_t)8 * D_MODEL;
#pragma unroll
        for (int nt = 0; nt < 8; nt++) {
            *(float2*)(C0 + nt * 8 + 2 * t) = make_float2(acc[mt][nt][0], acc[mt][nt][1]);
            *(float2*)(C1 + nt * 8 + 2 * t) = make_float2(acc[mt][nt][2], acc[mt][nt][3]);
        }
    }
}

__global__ __launch_bounds__(256) void gemm_qkv_f16(
    const float* __restrict__ x,
    const float* __restrict__ wq,
    const float* __restrict__ wk,
    const float* __restrict__ wv,
    float* __restrict__ q,
    float* __restrict__ k,
    float* __restrict__ v)
{
    const float* B = (blockIdx.z == 0) ? wq : (blockIdx.z == 1) ? wk : wv;
    float*       C = (blockIdx.z == 0) ? q  : (blockIdx.z == 1) ? k  : v;
    gemm_f16_body(x, B, C, blockIdx.y * 128, blockIdx.x * 128);
}

__global__ __launch_bounds__(256) void gemm_o_f16(
    const float* __restrict__ A,
    const float* __restrict__ B,
    float* __restrict__ C)
{
    gemm_f16_body(A, B, C, blockIdx.y * 128, blockIdx.x * 128);
}

// ---------------------------------------------------------------------------
// Flash attention, fp16 mma m16n8k16.
// grid = (SEQ/128, N_HEADS, BATCH), 256 threads = 8 warps x 16 q-rows.
// K smem [key][d] halves (stride 72), V transposed [d][key] (stride 72).
// PV A-fragments come straight from the S C-fragments (no shuffles).
// ---------------------------------------------------------------------------
__global__ __launch_bounds__(256) void flash_attn_f16(
    const float* __restrict__ Q,
    const float* __restrict__ K,
    const float* __restrict__ V,
    float* __restrict__ O)
{
    __shared__ __half Ks[64][72];
    __shared__ __half Vt[64][72];   // [d][key]

    const int qb   = gridDim.x - 1 - blockIdx.x;   // big tiles first
    const int h    = blockIdx.y;
    const int b    = blockIdx.z;
    const int tid  = threadIdx.x;
    const int warp = tid >> 5;
    const int lane = tid & 31;
    const int g    = lane >> 2;
    const int t    = lane & 3;
    const int q0   = warp * 16;

    const size_t base = ((size_t)b * SEQ) * D_MODEL + (size_t)h * HEAD_DIM;

    const int frow = (lane & 7) + ((lane >> 4) << 3);
    const int fch  = ((lane >> 3) & 1) * 8;
    uint32_t kAd[4], vAd[4];
#pragma unroll
    for (int np = 0; np < 4; np++) {
        kAd[np] = smem_u32(&Ks[np * 16 + frow][fch]);
        vAd[np] = smem_u32(&Vt[np * 16 + frow][fch]);
    }

    // Q fragments: 4 k16-chunks over d=64, pre-scaled by 1/8
    unsigned qa[4][4];
    {
        const float* Qp = Q + base + (size_t)(qb * 128 + q0) * D_MODEL;
#pragma unroll
        for (int kc = 0; kc < 4; kc++) {
            int c0 = kc * 16 + 2 * t;
            const float* r0 = Qp + (size_t)g * D_MODEL;
            const float* r1 = Qp + (size_t)(g + 8) * D_MODEL;
            qa[kc][0] = f22u(r0[c0] * 0.125f,     r0[c0 + 1] * 0.125f);
            qa[kc][1] = f22u(r1[c0] * 0.125f,     r1[c0 + 1] * 0.125f);
            qa[kc][2] = f22u(r0[c0 + 8] * 0.125f, r0[c0 + 9] * 0.125f);
            qa[kc][3] = f22u(r1[c0 + 8] * 0.125f, r1[c0 + 9] * 0.125f);
        }
    }

    float o[8][4];
#pragma unroll
    for (int nt = 0; nt < 8; nt++)
#pragma unroll
        for (int j = 0; j < 4; j++) o[nt][j] = 0.f;

    float m0 = -1e30f, m1 = -1e30f, l0 = 0.f, l1 = 0.f;

    const int kbmax = 2 * qb + 1;
    const int warp_max_row = qb * 128 + q0 + 15;

    float4 kreg[4], vreg[4];
#pragma unroll
    for (int j = 0; j < 4; j++) {
        int i = tid + j * 256;
        int row = i >> 4, d = (i & 15) * 4;
        kreg[j] = *(const float4*)(K + base + (size_t)row * D_MODEL + d);
        vreg[j] = *(const float4*)(V + base + (size_t)row * D_MODEL + d);
    }

    for (int kb = 0; kb <= kbmax; kb++) {
        __syncthreads();   // prior readers done
#pragma unroll
        for (int j = 0; j < 4; j++) {
            int i = tid + j * 256;
            int row = i >> 4, d = (i & 15) * 4;
            *(uint2*)&Ks[row][d] = make_uint2(f22u(kreg[j].x, kreg[j].y),
                                              f22u(kreg[j].z, kreg[j].w));
            Vt[d    ][row] = __float2half_rn(vreg[j].x);
            Vt[d + 1][row] = __float2half_rn(vreg[j].y);
            Vt[d + 2][row] = __float2half_rn(vreg[j].z);
            Vt[d + 3][row] = __float2half_rn(vreg[j].w);
        }
        __syncthreads();

        if (kb < kbmax) {   // prefetch next tile
#pragma unroll
            for (int j = 0; j < 4; j++) {
                int i = tid + j * 256;
                int row = (kb + 1) * 64 + (i >> 4);
                int d = (i & 15) * 4;
                kreg[j] = *(const float4*)(K + base + (size_t)row * D_MODEL + d);
                vreg[j] = *(const float4*)(V + base + (size_t)row * D_MODEL + d);
            }
        }

        if (kb * 64 > warp_max_row) continue;   // warp fully masked

        // ---- S = Q K^T ----
        float s[8][4];
#pragma unroll
        for (int nt = 0; nt < 8; nt++)
#pragma unroll
            for (int j = 0; j < 4; j++) s[nt][j] = 0.f;

#pragma unroll
        for (int kc = 0; kc < 4; kc++) {
            unsigned bf[8][2];
#pragma unroll
            for (int np = 0; np < 4; np++)
                ldsm4(bf[np*2][0], bf[np*2][1], bf[np*2+1][0], bf[np*2+1][1],
                      kAd[np] + kc * 32);
#pragma unroll
            for (int nt = 0; nt < 8; nt++)
                mma_f16(s[nt], qa[kc][0], qa[kc][1], qa[kc][2], qa[kc][3],
                        bf[nt][0], bf[nt][1]);
        }

        // ---- causal mask (diagonal region) ----
        if (kb >= 2 * qb) {
            int rg0 = qb * 128 + q0 + g;
            int rg1 = rg0 + 8;
#pragma unroll
            for (int nt = 0; nt < 8; nt++) {
                int cg = kb * 64 + nt * 8 + 2 * t;
                if (cg     > rg0) s[nt][0] = -1e30f;
                if (cg + 1 > rg0) s[nt][1] = -1e30f;
                if (cg     > rg1) s[nt][2] = -1e30f;
                if (cg + 1 > rg1) s[nt][3] = -1e30f;
            }
        }

        // ---- online softmax ----
        float mn0 = m0, mn1 = m1;
#pragma unroll
        for (int nt = 0; nt < 8; nt++) {
            mn0 = fmaxf(mn0, fmaxf(s[nt][0], s[nt][1]));
            mn1 = fmaxf(mn1, fmaxf(s[nt][2], s[nt][3]));
        }
        mn0 = fmaxf(mn0, __shfl_xor_sync(FULLMASK, mn0, 1));
        mn0 = fmaxf(mn0, __shfl_xor_sync(FULLMASK, mn0, 2));
        mn1 = fmaxf(mn1, __shfl_xor_sync(FULLMASK, mn1, 1));
        mn1 = fmaxf(mn1, __shfl_xor_sync(FULLMASK, mn1, 2));

        float a0s = __expf(m0 - mn0);
        float a1s = __expf(m1 - mn1);
        float ps0 = 0.f, ps1 = 0.f;
#pragma unroll
        for (int nt = 0; nt < 8; nt++) {
            s[nt][0] = __expf(s[nt][0] - mn0);
            s[nt][1] = __expf(s[nt][1] - mn0);
            s[nt][2] = __expf(s[nt][2] - mn1);
            s[nt][3] = __expf(s[nt][3] - mn1);
            ps0 += s[nt][0] + s[nt][1];
            ps1 += s[nt][2] + s[nt][3];
        }
        ps0 += __shfl_xor_sync(FULLMASK, ps0, 1);
        ps0 += __shfl_xor_sync(FULLMASK, ps0, 2);
        ps1 += __shfl_xor_sync(FULLMASK, ps1, 1);
        ps1 += __shfl_xor_sync(FULLMASK, ps1, 2);
        l0 = l0 * a0s + ps0;
        l1 = l1 * a1s + ps1;
        m0 = mn0; m1 = mn1;
#pragma unroll
        for (int nt = 0; nt < 8; nt++) {
            o[nt][0] *= a0s; o[nt][1] *= a0s;
            o[nt][2] *= a1s; o[nt][3] *= a1s;
        }

        // ---- O += P V : A-frags direct from S C-frags ----
#pragma unroll
        for (int kc = 0; kc < 4; kc++) {
            unsigned a0 = f22u(s[2*kc    ][0], s[2*kc    ][1]);
            unsigned a1 = f22u(s[2*kc    ][2], s[2*kc    ][3]);
            unsigned a2 = f22u(s[2*kc + 1][0], s[2*kc + 1][1]);
            unsigned a3 = f22u(s[2*kc + 1][2], s[2*kc + 1][3]);
            unsigned bf[8][2];
#pragma unroll
            for (int np = 0; np < 4; np++)
                ldsm4(bf[np*2][0], bf[np*2][1], bf[np*2+1][0], bf[np*2+1][1],
                      vAd[np] + kc * 32);
#pragma unroll
            for (int nt = 0; nt < 8; nt++)
                mma_f16(o[nt], a0, a1, a2, a3, bf[nt][0], bf[nt][1]);
        }
    }

    // ---- normalize + write ----
    float inv0 = 1.f / l0;
    float inv1 = 1.f / l1;
    float* Op = O + base + (size_t)(qb * 128 + q0) * D_MODEL;
#pragma unroll
    for (int nt = 0; nt < 8; nt++) {
        *(float2*)(Op + (size_t)g       * D_MODEL + nt * 8 + 2 * t) =
            make_float2(o[nt][0] * inv0, o[nt][1] * inv0);
        *(float2*)(Op + (size_t)(g + 8) * D_MODEL + nt * 8 + 2 * t) =
            make_float2(o[nt][2] * inv1, o[nt][3] * inv1);
    }
}

// ---------------------------------------------------------------------------
extern "C" void kernel_launch(void* const* d_in, const int* in_sizes, int n_in,
                              void* d_out, int out_size)
{
    const float* x  = (const float*)d_in[0];
    const float* wq = (const float*)d_in[1];
    const float* wk = (const float*)d_in[2];
    const float* wv = (const float*)d_in[3];
    const float* wo = (const float*)d_in[4];
    float* out = (float*)d_out;

    float *q, *k, *v, *ao;
    cudaGetSymbolAddress((void**)&q,  g_q);
    cudaGetSymbolAddress((void**)&k,  g_k);
    cudaGetSymbolAddress((void**)&v,  g_v);
    cudaGetSymbolAddress((void**)&ao, g_ao);

    dim3 gqkv(D_MODEL / 128, NTOK / 128, 3);   // (8, 32, 3)
    gemm_qkv_f16<<<gqkv, 256>>>(x, wq, wk, wv, q, k, v);

    dim3 ga(SEQ / 128, N_HEADS, BATCH);        // (16, 16, 2)
    flash_attn_f16<<<ga, 256>>>(q, k, v, ao);

    dim3 go(D_MODEL / 128, NTOK / 128);        // (8, 32)
    gemm_o_f16<<<go, 256>>>(ao, wo, out);
}

// round 8
// speedup vs baseline: 16.0982x; 1.5197x over previous
#include <cuda_runtime.h>
#include <cuda_fp16.h>
#include <cstdint>

#define D_MODEL  1024
#define N_HEADS  16
#define HEAD_DIM 64
#define BATCH    2
#define SEQ      2048
#define NTOK     (BATCH * SEQ)   // 4096
#define FULLMASK 0xffffffffu

#define N_X  (NTOK * D_MODEL)        // 4194304
#define N_W  (D_MODEL * D_MODEL)     // 1048576

// fp16 scratch (no cudaMalloc allowed)
__device__ __half g_xh [N_X];
__device__ __half g_wh [4 * N_W];    // wq|wk|wv|wo
__device__ __half g_qh [N_X];
__device__ __half g_kh [N_X];
__device__ __half g_vh [N_X];
__device__ __half g_aoh[N_X];

// ---------------------------------------------------------------------------
// helpers
// ---------------------------------------------------------------------------
__device__ __forceinline__ uint32_t smem_u32(const void* p) {
    return (uint32_t)__cvta_generic_to_shared(p);
}
__device__ __forceinline__ unsigned f22u(float a, float b) {
    __half2 h = __floats2half2_rn(a, b);
    return *reinterpret_cast<unsigned*>(&h);
}
__device__ __forceinline__ void mma_f16(float c[4],
                                        unsigned a0, unsigned a1, unsigned a2, unsigned a3,
                                        unsigned b0, unsigned b1) {
    asm volatile(
        "mma.sync.aligned.m16n8k16.row.col.f32.f16.f16.f32 "
        "{%0,%1,%2,%3}, {%4,%5,%6,%7}, {%8,%9}, {%0,%1,%2,%3};"
        : "+f"(c[0]), "+f"(c[1]), "+f"(c[2]), "+f"(c[3])
        : "r"(a0), "r"(a1), "r"(a2), "r"(a3), "r"(b0), "r"(b1));
}
__device__ __forceinline__ void ldsm4(unsigned& r0, unsigned& r1, unsigned& r2, unsigned& r3,
                                      uint32_t addr) {
    asm volatile("ldmatrix.sync.aligned.m8n8.x4.shared.b16 {%0,%1,%2,%3}, [%4];"
                 : "=r"(r0), "=r"(r1), "=r"(r2), "=r"(r3) : "r"(addr));
}
__device__ __forceinline__ void cp16(uint32_t dst, const void* src) {
    asm volatile("cp.async.cg.shared.global [%0], [%1], 16;" :: "r"(dst), "l"(src));
}
__device__ __forceinline__ void cp_commit() {
    asm volatile("cp.async.commit_group;" ::: "memory");
}
__device__ __forceinline__ void cp_wait1() {
    asm volatile("cp.async.wait_group 1;" ::: "memory");
}

// ---------------------------------------------------------------------------
// fp32 -> fp16 conversion: x (4M) + 4 weights (1M each), 4 elems/thread
// ---------------------------------------------------------------------------
__global__ __launch_bounds__(256) void cvt_f16(
    const float* __restrict__ x,
    const float* __restrict__ wq, const float* __restrict__ wk,
    const float* __restrict__ wv, const float* __restrict__ wo,
    __half* __restrict__ xh, __half* __restrict__ wh)
{
    size_t i4 = ((size_t)blockIdx.x * 256 + threadIdx.x) * 4;
    const float* src;
    __half* dst;
    if (i4 < N_X) { src = x + i4; dst = xh + i4; }
    else {
        size_t j = i4 - N_X;
        int w = (int)(j >> 20);
        const float* ws = (w == 0) ? wq : (w == 1) ? wk : (w == 2) ? wv : wo;
        src = ws + (j & (N_W - 1));
        dst = wh + j;
    }
    float4 v = *(const float4*)src;
    *(uint2*)dst = make_uint2(f22u(v.x, v.y), f22u(v.z, v.w));
}

// ---------------------------------------------------------------------------
// fp16 GEMM with cp.async pipeline:
// C[N,D] = A[N,K] * B[D,K]^T, fp16 in, 128x128 tile, BK=64 halves,
// 3-stage smem pipeline, XOR-16B-chunk swizzle, 256 thr (8 warps, 4m x 2n),
// warp tile 32x64. OUT_F16 selects fp16 or fp32 output.
// ---------------------------------------------------------------------------
#define STAGEB 32768u            // bytes per stage (A 16KB + B 16KB)
#define GEMM_DSM (3 * 32768)     // 96 KB

template <bool OUT_F16>
__global__ __launch_bounds__(256, 2) void gemm_f16(
    const __half* __restrict__ A,
    const __half* __restrict__ B,
    void* __restrict__ Cv,
    int zsel)                    // for qkv: 0/1/2 selects B,C offset; -1: plain
{
    extern __shared__ __half dsm[];
    const uint32_t sb = smem_u32(dsm);

    const int tid  = threadIdx.x;
    const int warp = tid >> 5;
    const int lane = tid & 31;
    const int g    = lane >> 2;
    const int t    = lane & 3;
    const int wm   = (warp & 3) * 32;
    const int wn   = (warp >> 2) * 64;
    const int m0   = blockIdx.y * 128;
    const int n0   = blockIdx.x * 128;

    // global->smem mapping: 4 chunks of 8 halves per thread per matrix
    const int row = tid >> 1;
    const int cb  = (tid & 1) * 4;
    const int rsw = row & 7;
    const __half* Ap = A + (size_t)(m0 + row) * D_MODEL + cb * 8;
    const __half* Bp = B + (size_t)(n0 + row) * D_MODEL + cb * 8;
    const uint32_t dRow = (uint32_t)row * 128u;

    // ldmatrix addressing
    uint32_t aOff[2]; int aSw[2];
#pragma unroll
    for (int mt = 0; mt < 2; mt++) {
        int r = wm + mt * 16 + (lane & 15);
        aOff[mt] = (uint32_t)r * 128u; aSw[mt] = r & 7;
    }
    const int hsA = lane >> 4;
    const int frow = (lane & 7) + ((lane >> 4) << 3);
    const int hsB = (lane >> 3) & 1;
    uint32_t bOff[4]; int bSw[4];
#pragma unroll
    for (int np = 0; np < 4; np++) {
        int r = wn + np * 16 + frow;
        bOff[np] = (uint32_t)r * 128u + 16384u; bSw[np] = r & 7;
    }

    float acc[2][8][4] = {};

    // prologue: stages 0,1
#pragma unroll
    for (int s = 0; s < 2; s++) {
        const uint32_t ab = sb + (uint32_t)s * STAGEB;
#pragma unroll
        for (int j = 0; j < 4; j++) {
            uint32_t sw = (uint32_t)((cb + j) ^ rsw) << 4;
            cp16(ab + dRow + sw,          Ap + s * 64 + j * 8);
            cp16(ab + 16384u + dRow + sw, Bp + s * 64 + j * 8);
        }
        cp_commit();
    }

    for (int s = 0; s < 16; s++) {
        cp_wait1();
        __syncthreads();
        const uint32_t stg = sb + (uint32_t)(s % 3) * STAGEB;
#pragma unroll
        for (int kc = 0; kc < 4; kc++) {
            unsigned af[2][4];
#pragma unroll
            for (int mt = 0; mt < 2; mt++)
                ldsm4(af[mt][0], af[mt][1], af[mt][2], af[mt][3],
                      stg + aOff[mt] + ((uint32_t)((kc * 2 + hsA) ^ aSw[mt]) << 4));
            unsigned bf[8][2];
#pragma unroll
            for (int np = 0; np < 4; np++)
                ldsm4(bf[np*2][0], bf[np*2][1], bf[np*2+1][0], bf[np*2+1][1],
                      stg + bOff[np] + ((uint32_t)((kc * 2 + hsB) ^ bSw[np]) << 4));
#pragma unroll
            for (int mt = 0; mt < 2; mt++)
#pragma unroll
                for (int nt = 0; nt < 8; nt++)
                    mma_f16(acc[mt][nt], af[mt][0], af[mt][1], af[mt][2], af[mt][3],
                            bf[nt][0], bf[nt][1]);
        }
        if (s + 2 < 16) {
            const int sn = s + 2;
            const uint32_t ab = sb + (uint32_t)(sn % 3) * STAGEB;
#pragma unroll
            for (int j = 0; j < 4; j++) {
                uint32_t sw = (uint32_t)((cb + j) ^ rsw) << 4;
                cp16(ab + dRow + sw,          Ap + sn * 64 + j * 8);
                cp16(ab + 16384u + dRow + sw, Bp + sn * 64 + j * 8);
            }
            cp_commit();
        }
    }

    // epilogue
#pragma unroll
    for (int mt = 0; mt < 2; mt++) {
#pragma unroll
        for (int half8 = 0; half8 < 2; half8++) {
            size_t r = (size_t)(m0 + wm + mt * 16 + g + half8 * 8);
            if (OUT_F16) {
                __half* Cp = (__half*)Cv + r * D_MODEL + n0 + wn;
#pragma unroll
                for (int nt = 0; nt < 8; nt++)
                    *(unsigned*)(Cp + nt * 8 + 2 * t) =
                        f22u(acc[mt][nt][half8 * 2], acc[mt][nt][half8 * 2 + 1]);
            } else {
                float* Cp = (float*)Cv + r * D_MODEL + n0 + wn;
#pragma unroll
                for (int nt = 0; nt < 8; nt++)
                    *(float2*)(Cp + nt * 8 + 2 * t) =
                        make_float2(acc[mt][nt][half8 * 2], acc[mt][nt][half8 * 2 + 1]);
            }
        }
    }
    (void)zsel;
}

// QKV wrapper: z selects weight slab + output
__global__ __launch_bounds__(256, 2) void gemm_qkv_f16(
    const __half* __restrict__ xh,
    const __half* __restrict__ wh,
    __half* __restrict__ qh, __half* __restrict__ kh, __half* __restrict__ vh);

// (separate definition to keep one compiled body — forward through gemm_f16 logic)
// Simpler: implement as its own kernel calling the same inline body is complex;
// instead we just relaunch gemm_f16<true> 3 times from host with different ptrs.

// ---------------------------------------------------------------------------
// Flash attention, fp16 in/out. grid = (SEQ/128, N_HEADS, BATCH), 256 thr.
// K smem [key][d] (stride 72 halves, (r+c)%8 bank spread), V transposed [d][key].
// ---------------------------------------------------------------------------
__global__ __launch_bounds__(256, 2) void flash_attn_f16(
    const __half* __restrict__ Q,
    const __half* __restrict__ K,
    const __half* __restrict__ V,
    __half* __restrict__ O)
{
    __shared__ __half Ks[64][72];
    __shared__ __half Vt[64][72];

    const int qb   = gridDim.x - 1 - blockIdx.x;
    const int h    = blockIdx.y;
    const int b    = blockIdx.z;
    const int tid  = threadIdx.x;
    const int warp = tid >> 5;
    const int lane = tid & 31;
    const int g    = lane >> 2;
    const int t    = lane & 3;
    const int q0   = warp * 16;

    const size_t base = ((size_t)b * SEQ) * D_MODEL + (size_t)h * HEAD_DIM;

    const int frow = (lane & 7) + ((lane >> 4) << 3);
    const int fch  = ((lane >> 3) & 1) * 8;
    uint32_t kAd[4], vAd[4];
#pragma unroll
    for (int np = 0; np < 4; np++) {
        kAd[np] = smem_u32(&Ks[np * 16 + frow][fch]);
        vAd[np] = smem_u32(&Vt[np * 16 + frow][fch]);
    }

    // Q fragments (scaled by 1/8)
    unsigned qa[4][4];
    {
        const __half2 sc = __half2half2(__float2half(0.125f));
        const __half* Qp = Q + base + (size_t)(qb * 128 + q0) * D_MODEL;
#pragma unroll
        for (int kc = 0; kc < 4; kc++) {
            int c0 = kc * 16 + 2 * t;
            const __half* r0 = Qp + (size_t)g * D_MODEL;
            const __half* r1 = Qp + (size_t)(g + 8) * D_MODEL;
            __half2 h0 = __hmul2(*(const __half2*)(r0 + c0), sc);
            __half2 h1 = __hmul2(*(const __half2*)(r1 + c0), sc);
            __half2 h2 = __hmul2(*(const __half2*)(r0 + c0 + 8), sc);
            __half2 h3 = __hmul2(*(const __half2*)(r1 + c0 + 8), sc);
            qa[kc][0] = *(unsigned*)&h0; qa[kc][1] = *(unsigned*)&h1;
            qa[kc][2] = *(unsigned*)&h2; qa[kc][3] = *(unsigned*)&h3;
        }
    }

    float o[8][4] = {};
    float m0 = -1e30f, m1 = -1e30f, l0 = 0.f, l1 = 0.f;

    const int kbmax = 2 * qb + 1;
    const int warp_max_row = qb * 128 + q0 + 15;

    uint4 kreg[2], vreg[2];
#pragma unroll
    for (int j = 0; j < 2; j++) {
        int i = tid + j * 256;
        int row = i >> 3, ch = i & 7;
        kreg[j] = *(const uint4*)(K + base + (size_t)row * D_MODEL + ch * 8);
        vreg[j] = *(const uint4*)(V + base + (size_t)row * D_MODEL + ch * 8);
    }

    for (int kb = 0; kb <= kbmax; kb++) {
        __syncthreads();
#pragma unroll
        for (int j = 0; j < 2; j++) {
            int i = tid + j * 256;
            int row = i >> 3, ch = i & 7;
            *(uint2*)&Ks[row][ch * 8]     = make_uint2(kreg[j].x, kreg[j].y);
            *(uint2*)&Ks[row][ch * 8 + 4] = make_uint2(kreg[j].z, kreg[j].w);
            const __half* vh = (const __half*)&vreg[j];
#pragma unroll
            for (int jj = 0; jj < 8; jj++)
                Vt[ch * 8 + jj][row] = vh[jj];
        }
        __syncthreads();

        if (kb < kbmax) {
#pragma unroll
            for (int j = 0; j < 2; j++) {
                int i = tid + j * 256;
                int row = (kb + 1) * 64 + (i >> 3);
                int ch = i & 7;
                kreg[j] = *(const uint4*)(K + base + (size_t)row * D_MODEL + ch * 8);
                vreg[j] = *(const uint4*)(V + base + (size_t)row * D_MODEL + ch * 8);
            }
        }

        if (kb * 64 > warp_max_row) continue;

        // ---- S = Q K^T ----
        float s[8][4] = {};
#pragma unroll
        for (int kc = 0; kc < 4; kc++) {
            unsigned bf[8][2];
#pragma unroll
            for (int np = 0; np < 4; np++)
                ldsm4(bf[np*2][0], bf[np*2][1], bf[np*2+1][0], bf[np*2+1][1],
                      kAd[np] + kc * 32);
#pragma unroll
            for (int nt = 0; nt < 8; nt++)
                mma_f16(s[nt], qa[kc][0], qa[kc][1], qa[kc][2], qa[kc][3],
                        bf[nt][0], bf[nt][1]);
        }

        if (kb >= 2 * qb) {
            int rg0 = qb * 128 + q0 + g;
            int rg1 = rg0 + 8;
#pragma unroll
            for (int nt = 0; nt < 8; nt++) {
                int cg = kb * 64 + nt * 8 + 2 * t;
                if (cg     > rg0) s[nt][0] = -1e30f;
                if (cg + 1 > rg0) s[nt][1] = -1e30f;
                if (cg     > rg1) s[nt][2] = -1e30f;
                if (cg + 1 > rg1) s[nt][3] = -1e30f;
            }
        }

        float mn0 = m0, mn1 = m1;
#pragma unroll
        for (int nt = 0; nt < 8; nt++) {
            mn0 = fmaxf(mn0, fmaxf(s[nt][0], s[nt][1]));
            mn1 = fmaxf(mn1, fmaxf(s[nt][2], s[nt][3]));
        }
        mn0 = fmaxf(mn0, __shfl_xor_sync(FULLMASK, mn0, 1));
        mn0 = fmaxf(mn0, __shfl_xor_sync(FULLMASK, mn0, 2));
        mn1 = fmaxf(mn1, __shfl_xor_sync(FULLMASK, mn1, 1));
        mn1 = fmaxf(mn1, __shfl_xor_sync(FULLMASK, mn1, 2));

        float a0s = __expf(m0 - mn0);
        float a1s = __expf(m1 - mn1);
        float ps0 = 0.f, ps1 = 0.f;
#pragma unroll
        for (int nt = 0; nt < 8; nt++) {
            s[nt][0] = __expf(s[nt][0] - mn0);
            s[nt][1] = __expf(s[nt][1] - mn0);
            s[nt][2] = __expf(s[nt][2] - mn1);
            s[nt][3] = __expf(s[nt][3] - mn1);
            ps0 += s[nt][0] + s[nt][1];
            ps1 += s[nt][2] + s[nt][3];
        }
        ps0 += __shfl_xor_sync(FULLMASK, ps0, 1);
        ps0 += __shfl_xor_sync(FULLMASK, ps0, 2);
        ps1 += __shfl_xor_sync(FULLMASK, ps1, 1);
        ps1 += __shfl_xor_sync(FULLMASK, ps1, 2);
        l0 = l0 * a0s + ps0;
        l1 = l1 * a1s + ps1;
        m0 = mn0; m1 = mn1;
#pragma unroll
        for (int nt = 0; nt < 8; nt++) {
            o[nt][0] *= a0s; o[nt][1] *= a0s;
            o[nt][2] *= a1s; o[nt][3] *= a1s;
        }

        // ---- O += P V (A-frags direct from S C-frags) ----
#pragma unroll
        for (int kc = 0; kc < 4; kc++) {
            unsigned a0 = f22u(s[2*kc    ][0], s[2*kc    ][1]);
            unsigned a1 = f22u(s[2*kc    ][2], s[2*kc    ][3]);
            unsigned a2 = f22u(s[2*kc + 1][0], s[2*kc + 1][1]);
            unsigned a3 = f22u(s[2*kc + 1][2], s[2*kc + 1][3]);
            unsigned bf[8][2];
#pragma unroll
            for (int np = 0; np < 4; np++)
                ldsm4(bf[np*2][0], bf[np*2][1], bf[np*2+1][0], bf[np*2+1][1],
                      vAd[np] + kc * 32);
#pragma unroll
            for (int nt = 0; nt < 8; nt++)
                mma_f16(o[nt], a0, a1, a2, a3, bf[nt][0], bf[nt][1]);
        }
    }

    float inv0 = 1.f / l0;
    float inv1 = 1.f / l1;
    __half* Op = O + base + (size_t)(qb * 128 + q0) * D_MODEL;
#pragma unroll
    for (int nt = 0; nt < 8; nt++) {
        *(unsigned*)(Op + (size_t)g       * D_MODEL + nt * 8 + 2 * t) =
            f22u(o[nt][0] * inv0, o[nt][1] * inv0);
        *(unsigned*)(Op + (size_t)(g + 8) * D_MODEL + nt * 8 + 2 * t) =
            f22u(o[nt][2] * inv1, o[nt][3] * inv1);
    }
}

// ---------------------------------------------------------------------------
extern "C" void kernel_launch(void* const* d_in, const int* in_sizes, int n_in,
                              void* d_out, int out_size)
{
    const float* x  = (const float*)d_in[0];
    const float* wq = (const float*)d_in[1];
    const float* wk = (const float*)d_in[2];
    const float* wv = (const float*)d_in[3];
    const float* wo = (const float*)d_in[4];
    float* out = (float*)d_out;

    __half *xh, *wh, *qh, *kh, *vh, *aoh;
    cudaGetSymbolAddress((void**)&xh,  g_xh);
    cudaGetSymbolAddress((void**)&wh,  g_wh);
    cudaGetSymbolAddress((void**)&qh,  g_qh);
    cudaGetSymbolAddress((void**)&kh,  g_kh);
    cudaGetSymbolAddress((void**)&vh,  g_vh);
    cudaGetSymbolAddress((void**)&aoh, g_aoh);

    cudaFuncSetAttribute(gemm_f16<true>,  cudaFuncAttributeMaxDynamicSharedMemorySize, GEMM_DSM);
    cudaFuncSetAttribute(gemm_f16<false>, cudaFuncAttributeMaxDynamicSharedMemorySize, GEMM_DSM);

    // 1) convert inputs to fp16
    cvt_f16<<<(N_X + 4 * N_W) / (256 * 4), 256>>>(x, wq, wk, wv, wo, xh, wh);

    // 2) Q/K/V projections (fp16 out)
    dim3 gg(D_MODEL / 128, NTOK / 128);        // (8, 32)
    gemm_f16<true><<<gg, 256, GEMM_DSM>>>(xh, wh,           qh, 0);
    gemm_f16<true><<<gg, 256, GEMM_DSM>>>(xh, wh + N_W,     kh, 1);
    gemm_f16<true><<<gg, 256, GEMM_DSM>>>(xh, wh + 2 * N_W, vh, 2);

    // 3) attention (fp16 in/out)
    dim3 ga(SEQ / 128, N_HEADS, BATCH);        // (16, 16, 2)
    flash_attn_f16<<<ga, 256>>>(qh, kh, vh, aoh);

    // 4) output projection (fp32 out)
    gemm_f16<false><<<gg, 256, GEMM_DSM>>>(aoh, wh + 3 * N_W, out, 3);
}

// round 9
// speedup vs baseline: 20.1716x; 1.2530x over previous
#include <cuda_runtime.h>
#include <cuda_fp16.h>
#include <cstdint>

#define D_MODEL  1024
#define N_HEADS  16
#define HEAD_DIM 64
#define BATCH    2
#define SEQ      2048
#define NTOK     (BATCH * SEQ)   // 4096
#define FULLMASK 0xffffffffu

#define N_X  (NTOK * D_MODEL)        // 4194304
#define N_W  (D_MODEL * D_MODEL)     // 1048576

// fp16 scratch (no cudaMalloc allowed)
__device__ __half g_xh [N_X];
__device__ __half g_wh [4 * N_W];    // wq|wk|wv|wo (row-contiguous)
__device__ __half g_qh [N_X];
__device__ __half g_kh [N_X];
__device__ __half g_vh [N_X];
__device__ __half g_aoh[N_X];

// ---------------------------------------------------------------------------
// helpers
// ---------------------------------------------------------------------------
__device__ __forceinline__ uint32_t smem_u32(const void* p) {
    return (uint32_t)__cvta_generic_to_shared(p);
}
__device__ __forceinline__ unsigned f22u(float a, float b) {
    __half2 h = __floats2half2_rn(a, b);
    return *reinterpret_cast<unsigned*>(&h);
}
__device__ __forceinline__ float ex2(float x) {
    float y;
    asm("ex2.approx.ftz.f32 %0, %1;" : "=f"(y) : "f"(x));
    return y;
}
__device__ __forceinline__ void mma_f16(float c[4],
                                        unsigned a0, unsigned a1, unsigned a2, unsigned a3,
                                        unsigned b0, unsigned b1) {
    asm volatile(
        "mma.sync.aligned.m16n8k16.row.col.f32.f16.f16.f32 "
        "{%0,%1,%2,%3}, {%4,%5,%6,%7}, {%8,%9}, {%0,%1,%2,%3};"
        : "+f"(c[0]), "+f"(c[1]), "+f"(c[2]), "+f"(c[3])
        : "r"(a0), "r"(a1), "r"(a2), "r"(a3), "r"(b0), "r"(b1));
}
__device__ __forceinline__ void ldsm4(unsigned& r0, unsigned& r1, unsigned& r2, unsigned& r3,
                                      uint32_t addr) {
    asm volatile("ldmatrix.sync.aligned.m8n8.x4.shared.b16 {%0,%1,%2,%3}, [%4];"
                 : "=r"(r0), "=r"(r1), "=r"(r2), "=r"(r3) : "r"(addr));
}
__device__ __forceinline__ void ldsm4t(unsigned& r0, unsigned& r1, unsigned& r2, unsigned& r3,
                                       uint32_t addr) {
    asm volatile("ldmatrix.sync.aligned.m8n8.x4.trans.shared.b16 {%0,%1,%2,%3}, [%4];"
                 : "=r"(r0), "=r"(r1), "=r"(r2), "=r"(r3) : "r"(addr));
}
__device__ __forceinline__ void cp16(uint32_t dst, const void* src) {
    asm volatile("cp.async.cg.shared.global [%0], [%1], 16;" :: "r"(dst), "l"(src));
}
__device__ __forceinline__ void cp_commit() {
    asm volatile("cp.async.commit_group;" ::: "memory");
}
__device__ __forceinline__ void cp_wait0() {
    asm volatile("cp.async.wait_group 0;" ::: "memory");
}
__device__ __forceinline__ void cp_wait1() {
    asm volatile("cp.async.wait_group 1;" ::: "memory");
}

// ---------------------------------------------------------------------------
// fp32 -> fp16 conversion
// ---------------------------------------------------------------------------
__global__ __launch_bounds__(256) void cvt_f16(
    const float* __restrict__ x,
    const float* __restrict__ wq, const float* __restrict__ wk,
    const float* __restrict__ wv, const float* __restrict__ wo,
    __half* __restrict__ xh, __half* __restrict__ wh)
{
    size_t i4 = ((size_t)blockIdx.x * 256 + threadIdx.x) * 4;
    const float* src;
    __half* dst;
    if (i4 < N_X) { src = x + i4; dst = xh + i4; }
    else {
        size_t j = i4 - N_X;
        int w = (int)(j >> 20);
        const float* ws = (w == 0) ? wq : (w == 1) ? wk : (w == 2) ? wv : wo;
        src = ws + (j & (N_W - 1));
        dst = wh + j;
    }
    float4 v = *(const float4*)src;
    *(uint2*)dst = make_uint2(f22u(v.x, v.y), f22u(v.z, v.w));
}

// ---------------------------------------------------------------------------
// fp16 GEMM, cp.async 3-stage pipeline, 128x128 tile, BK=64, 256 thr.
// MODE 0: fused QKV (N=3072, fp16 out routed by n0>>10). MODE 1: fp32 out.
// ---------------------------------------------------------------------------
#define STAGEB 32768u
#define GEMM_DSM (3 * 32768)

template <int MODE>
__global__ __launch_bounds__(256, 2) void gemm_f16(
    const __half* __restrict__ A,
    const __half* __restrict__ B,
    __half* __restrict__ q, __half* __restrict__ k, __half* __restrict__ v,
    float* __restrict__ fout)
{
    extern __shared__ __half dsm[];
    const uint32_t sb = smem_u32(dsm);

    const int tid  = threadIdx.x;
    const int warp = tid >> 5;
    const int lane = tid & 31;
    const int g    = lane >> 2;
    const int t    = lane & 3;
    const int wm   = (warp & 3) * 32;
    const int wn   = (warp >> 2) * 64;
    const int m0   = blockIdx.y * 128;
    const int n0   = blockIdx.x * 128;

    const int row = tid >> 1;
    const int cb  = (tid & 1) * 4;
    const int rsw = row & 7;
    const __half* Ap = A + (size_t)(m0 + row) * D_MODEL + cb * 8;
    const __half* Bp = B + (size_t)(n0 + row) * D_MODEL + cb * 8;
    const uint32_t dRow = (uint32_t)row * 128u;

    uint32_t aOff[2]; int aSw[2];
#pragma unroll
    for (int mt = 0; mt < 2; mt++) {
        int r = wm + mt * 16 + (lane & 15);
        aOff[mt] = (uint32_t)r * 128u; aSw[mt] = r & 7;
    }
    const int hsA = lane >> 4;
    const int frow = (lane & 7) + ((lane >> 4) << 3);
    const int hsB = (lane >> 3) & 1;
    uint32_t bOff[4]; int bSw[4];
#pragma unroll
    for (int np = 0; np < 4; np++) {
        int r = wn + np * 16 + frow;
        bOff[np] = (uint32_t)r * 128u + 16384u; bSw[np] = r & 7;
    }

    float acc[2][8][4] = {};

#pragma unroll
    for (int s = 0; s < 2; s++) {
        const uint32_t ab = sb + (uint32_t)s * STAGEB;
#pragma unroll
        for (int j = 0; j < 4; j++) {
            uint32_t sw = (uint32_t)((cb + j) ^ rsw) << 4;
            cp16(ab + dRow + sw,          Ap + s * 64 + j * 8);
            cp16(ab + 16384u + dRow + sw, Bp + s * 64 + j * 8);
        }
        cp_commit();
    }

    for (int s = 0; s < 16; s++) {
        cp_wait1();
        __syncthreads();
        const uint32_t stg = sb + (uint32_t)(s % 3) * STAGEB;
#pragma unroll
        for (int kc = 0; kc < 4; kc++) {
            unsigned af[2][4];
#pragma unroll
            for (int mt = 0; mt < 2; mt++)
                ldsm4(af[mt][0], af[mt][1], af[mt][2], af[mt][3],
                      stg + aOff[mt] + ((uint32_t)((kc * 2 + hsA) ^ aSw[mt]) << 4));
            unsigned bf[8][2];
#pragma unroll
            for (int np = 0; np < 4; np++)
                ldsm4(bf[np*2][0], bf[np*2][1], bf[np*2+1][0], bf[np*2+1][1],
                      stg + bOff[np] + ((uint32_t)((kc * 2 + hsB) ^ bSw[np]) << 4));
#pragma unroll
            for (int mt = 0; mt < 2; mt++)
#pragma unroll
                for (int nt = 0; nt < 8; nt++)
                    mma_f16(acc[mt][nt], af[mt][0], af[mt][1], af[mt][2], af[mt][3],
                            bf[nt][0], bf[nt][1]);
        }
        if (s + 2 < 16) {
            const int sn = s + 2;
            const uint32_t ab = sb + (uint32_t)(sn % 3) * STAGEB;
#pragma unroll
            for (int j = 0; j < 4; j++) {
                uint32_t sw = (uint32_t)((cb + j) ^ rsw) << 4;
                cp16(ab + dRow + sw,          Ap + sn * 64 + j * 8);
                cp16(ab + 16384u + dRow + sw, Bp + sn * 64 + j * 8);
            }
            cp_commit();
        }
    }

    // epilogue
    if (MODE == 0) {
        const int sel  = n0 >> 10;
        __half* Cb = (sel == 0) ? q : (sel == 1) ? k : v;
        const int nloc = (n0 & 1023) + wn;
#pragma unroll
        for (int mt = 0; mt < 2; mt++)
#pragma unroll
            for (int half8 = 0; half8 < 2; half8++) {
                __half* Cp = Cb + (size_t)(m0 + wm + mt * 16 + g + half8 * 8) * D_MODEL + nloc;
#pragma unroll
                for (int nt = 0; nt < 8; nt++)
                    *(unsigned*)(Cp + nt * 8 + 2 * t) =
                        f22u(acc[mt][nt][half8 * 2], acc[mt][nt][half8 * 2 + 1]);
            }
    } else {
#pragma unroll
        for (int mt = 0; mt < 2; mt++)
#pragma unroll
            for (int half8 = 0; half8 < 2; half8++) {
                float* Cp = fout + (size_t)(m0 + wm + mt * 16 + g + half8 * 8) * D_MODEL + n0 + wn;
#pragma unroll
                for (int nt = 0; nt < 8; nt++)
                    *(float2*)(Cp + nt * 8 + 2 * t) =
                        make_float2(acc[mt][nt][half8 * 2], acc[mt][nt][half8 * 2 + 1]);
            }
    }
}

// ---------------------------------------------------------------------------
// Flash attention, fp16, cp.async 2-stage K/V pipeline, trans-ldmatrix PV.
// grid = (SEQ/128, N_HEADS, BATCH), 256 threads = 8 warps x 16 q-rows.
// K and V both stored [key][d] (stride 72 halves) per stage.
// ---------------------------------------------------------------------------
#define ASTR 72
#define ATILEB (64 * ASTR * 2)   // 9216 bytes

__global__ __launch_bounds__(256, 2) void flash_attn_f16(
    const __half* __restrict__ Q,
    const __half* __restrict__ K,
    const __half* __restrict__ V,
    __half* __restrict__ O)
{
    __shared__ __half Ks[2][64][ASTR];
    __shared__ __half Vs[2][64][ASTR];

    const int qb   = gridDim.x - 1 - blockIdx.x;   // big tiles first
    const int h    = blockIdx.y;
    const int b    = blockIdx.z;
    const int tid  = threadIdx.x;
    const int warp = tid >> 5;
    const int lane = tid & 31;
    const int g    = lane >> 2;
    const int t    = lane & 3;
    const int q0   = warp * 16;

    const size_t base = ((size_t)b * SEQ) * D_MODEL + (size_t)h * HEAD_DIM;

    // cp.async dst mapping: 2 chunks (16B) per thread per matrix
    const int c0r = (tid * 2)     >> 3, c0c = (tid * 2)     & 7;
    const int c1r = (tid * 2 + 1) >> 3, c1c = (tid * 2 + 1) & 7;
    const uint32_t kDst0 = smem_u32(&Ks[0][c0r][c0c * 8]);
    const uint32_t kDst1 = smem_u32(&Ks[0][c1r][c1c * 8]);
    const uint32_t vDst0 = smem_u32(&Vs[0][c0r][c0c * 8]);
    const uint32_t vDst1 = smem_u32(&Vs[0][c1r][c1c * 8]);
    const __half* Ksrc0 = K + base + (size_t)c0r * D_MODEL + c0c * 8;
    const __half* Ksrc1 = K + base + (size_t)c1r * D_MODEL + c1c * 8;
    const __half* Vsrc0 = V + base + (size_t)c0r * D_MODEL + c0c * 8;
    const __half* Vsrc1 = V + base + (size_t)c1r * D_MODEL + c1c * 8;

    // QK b-frag (non-trans) addressing
    const int frow = (lane & 7) + ((lane >> 4) << 3);
    const int fch  = ((lane >> 3) & 1) * 8;
    uint32_t kAd[4];
#pragma unroll
    for (int np = 0; np < 4; np++)
        kAd[np] = smem_u32(&Ks[0][np * 16 + frow][fch]);

    // PV b-frag (trans) addressing: row = lane&15 (k), col = (lane>>4)*8 (d)
    const uint32_t vAdBase = smem_u32(&Vs[0][lane & 15][((lane >> 4) << 3)]);

    // Q fragments scaled by 0.125 * log2(e)  (softmax in exp2 domain)
    unsigned qa[4][4];
    {
        const __half2 sc = __half2half2(__float2half(0.125f * 1.44269504f));
        const __half* Qp = Q + base + (size_t)(qb * 128 + q0) * D_MODEL;
#pragma unroll
        for (int kc = 0; kc < 4; kc++) {
            int c0 = kc * 16 + 2 * t;
            const __half* r0 = Qp + (size_t)g * D_MODEL;
            const __half* r1 = Qp + (size_t)(g + 8) * D_MODEL;
            __half2 h0 = __hmul2(*(const __half2*)(r0 + c0), sc);
            __half2 h1 = __hmul2(*(const __half2*)(r1 + c0), sc);
            __half2 h2 = __hmul2(*(const __half2*)(r0 + c0 + 8), sc);
            __half2 h3 = __hmul2(*(const __half2*)(r1 + c0 + 8), sc);
            qa[kc][0] = *(unsigned*)&h0; qa[kc][1] = *(unsigned*)&h1;
            qa[kc][2] = *(unsigned*)&h2; qa[kc][3] = *(unsigned*)&h3;
        }
    }

    float o[8][4] = {};
    float m0 = -1e30f, m1 = -1e30f, l0 = 0.f, l1 = 0.f;

    const int kbmax = 2 * qb + 1;
    const int warp_max_row = qb * 128 + q0 + 15;

    // prologue: stage 0 <- kb 0
    cp16(kDst0, Ksrc0); cp16(kDst1, Ksrc1);
    cp16(vDst0, Vsrc0); cp16(vDst1, Vsrc1);
    cp_commit();

    for (int kb = 0; kb <= kbmax; kb++) {
        cp_wait0();
        __syncthreads();   // data for kb ready; all readers of buffer kb-1 done

        if (kb < kbmax) {   // issue kb+1 into the other buffer
            const uint32_t boff = (uint32_t)((kb + 1) & 1) * ATILEB;
            const size_t goff = (size_t)(kb + 1) * 64 * D_MODEL;
            cp16(kDst0 + boff, Ksrc0 + goff); cp16(kDst1 + boff, Ksrc1 + goff);
            cp16(vDst0 + boff, Vsrc0 + goff); cp16(vDst1 + boff, Vsrc1 + goff);
            cp_commit();
        }

        if (kb * 64 > warp_max_row) continue;   // fully masked warp

        const uint32_t sbo = (uint32_t)(kb & 1) * ATILEB;

        // ---- S = Q K^T (exp2 domain) ----
        float s[8][4] = {};
#pragma unroll
        for (int kc = 0; kc < 4; kc++) {
            unsigned bf[8][2];
#pragma unroll
            for (int np = 0; np < 4; np++)
                ldsm4(bf[np*2][0], bf[np*2][1], bf[np*2+1][0], bf[np*2+1][1],
                      kAd[np] + sbo + kc * 32);
#pragma unroll
            for (int nt = 0; nt < 8; nt++)
                mma_f16(s[nt], qa[kc][0], qa[kc][1], qa[kc][2], qa[kc][3],
                        bf[nt][0], bf[nt][1]);
        }

        // ---- causal mask ----
        if (kb >= 2 * qb) {
            int rg0 = qb * 128 + q0 + g;
            int rg1 = rg0 + 8;
#pragma unroll
            for (int nt = 0; nt < 8; nt++) {
                int cg = kb * 64 + nt * 8 + 2 * t;
                if (cg     > rg0) s[nt][0] = -1e30f;
                if (cg + 1 > rg0) s[nt][1] = -1e30f;
                if (cg     > rg1) s[nt][2] = -1e30f;
                if (cg + 1 > rg1) s[nt][3] = -1e30f;
            }
        }

        // ---- online softmax (exp2) ----
        float mn0 = m0, mn1 = m1;
#pragma unroll
        for (int nt = 0; nt < 8; nt++) {
            mn0 = fmaxf(mn0, fmaxf(s[nt][0], s[nt][1]));
            mn1 = fmaxf(mn1, fmaxf(s[nt][2], s[nt][3]));
        }
        mn0 = fmaxf(mn0, __shfl_xor_sync(FULLMASK, mn0, 1));
        mn0 = fmaxf(mn0, __shfl_xor_sync(FULLMASK, mn0, 2));
        mn1 = fmaxf(mn1, __shfl_xor_sync(FULLMASK, mn1, 1));
        mn1 = fmaxf(mn1, __shfl_xor_sync(FULLMASK, mn1, 2));

        float a0s = ex2(m0 - mn0);
        float a1s = ex2(m1 - mn1);
        float ps0 = 0.f, ps1 = 0.f;
#pragma unroll
        for (int nt = 0; nt < 8; nt++) {
            s[nt][0] = ex2(s[nt][0] - mn0);
            s[nt][1] = ex2(s[nt][1] - mn0);
            s[nt][2] = ex2(s[nt][2] - mn1);
            s[nt][3] = ex2(s[nt][3] - mn1);
            ps0 += s[nt][0] + s[nt][1];
            ps1 += s[nt][2] + s[nt][3];
        }
        ps0 += __shfl_xor_sync(FULLMASK, ps0, 1);
        ps0 += __shfl_xor_sync(FULLMASK, ps0, 2);
        ps1 += __shfl_xor_sync(FULLMASK, ps1, 1);
        ps1 += __shfl_xor_sync(FULLMASK, ps1, 2);
        l0 = l0 * a0s + ps0;
        l1 = l1 * a1s + ps1;
        m0 = mn0; m1 = mn1;
#pragma unroll
        for (int nt = 0; nt < 8; nt++) {
            o[nt][0] *= a0s; o[nt][1] *= a0s;
            o[nt][2] *= a1s; o[nt][3] *= a1s;
        }

        // ---- O += P V  (B-frags via trans ldmatrix on V[key][d]) ----
#pragma unroll
        for (int kc = 0; kc < 4; kc++) {
            unsigned a0 = f22u(s[2*kc    ][0], s[2*kc    ][1]);
            unsigned a1 = f22u(s[2*kc    ][2], s[2*kc    ][3]);
            unsigned a2 = f22u(s[2*kc + 1][0], s[2*kc + 1][1]);
            unsigned a3 = f22u(s[2*kc + 1][2], s[2*kc + 1][3]);
            unsigned bf[8][2];
#pragma unroll
            for (int nt2 = 0; nt2 < 4; nt2++)
                ldsm4t(bf[nt2*2][0], bf[nt2*2][1], bf[nt2*2+1][0], bf[nt2*2+1][1],
                       vAdBase + sbo + (uint32_t)kc * (16 * ASTR * 2) + (uint32_t)nt2 * 32);
#pragma unroll
            for (int nt = 0; nt < 8; nt++)
                mma_f16(o[nt], a0, a1, a2, a3, bf[nt][0], bf[nt][1]);
        }
    }

    float inv0 = 1.f / l0;
    float inv1 = 1.f / l1;
    __half* Op = O + base + (size_t)(qb * 128 + q0) * D_MODEL;
#pragma unroll
    for (int nt = 0; nt < 8; nt++) {
        *(unsigned*)(Op + (size_t)g       * D_MODEL + nt * 8 + 2 * t) =
            f22u(o[nt][0] * inv0, o[nt][1] * inv0);
        *(unsigned*)(Op + (size_t)(g + 8) * D_MODEL + nt * 8 + 2 * t) =
            f22u(o[nt][2] * inv1, o[nt][3] * inv1);
    }
}

// ---------------------------------------------------------------------------
extern "C" void kernel_launch(void* const* d_in, const int* in_sizes, int n_in,
                              void* d_out, int out_size)
{
    const float* x  = (const float*)d_in[0];
    const float* wq = (const float*)d_in[1];
    const float* wk = (const float*)d_in[2];
    const float* wv = (const float*)d_in[3];
    const float* wo = (const float*)d_in[4];
    float* out = (float*)d_out;

    __half *xh, *wh, *qh, *kh, *vh, *aoh;
    cudaGetSymbolAddress((void**)&xh,  g_xh);
    cudaGetSymbolAddress((void**)&wh,  g_wh);
    cudaGetSymbolAddress((void**)&qh,  g_qh);
    cudaGetSymbolAddress((void**)&kh,  g_kh);
    cudaGetSymbolAddress((void**)&vh,  g_vh);
    cudaGetSymbolAddress((void**)&aoh, g_aoh);

    cudaFuncSetAttribute(gemm_f16<0>, cudaFuncAttributeMaxDynamicSharedMemorySize, GEMM_DSM);
    cudaFuncSetAttribute(gemm_f16<1>, cudaFuncAttributeMaxDynamicSharedMemorySize, GEMM_DSM);

    // 1) convert to fp16
    cvt_f16<<<(N_X + 4 * N_W) / (256 * 4), 256>>>(x, wq, wk, wv, wo, xh, wh);

    // 2) fused QKV projection (one launch, N=3072)
    dim3 gqkv(3 * D_MODEL / 128, NTOK / 128);   // (24, 32)
    gemm_f16<0><<<gqkv, 256, GEMM_DSM>>>(xh, wh, qh, kh, vh, nullptr);

    // 3) attention
    dim3 ga(SEQ / 128, N_HEADS, BATCH);          // (16, 16, 2)
    flash_attn_f16<<<ga, 256>>>(qh, kh, vh, aoh);

    // 4) output projection (fp32 out)
    dim3 go(D_MODEL / 128, NTOK / 128);          // (8, 32)
    gemm_f16<1><<<go, 256, GEMM_DSM>>>(aoh, wh + 3 * N_W, nullptr, nullptr, nullptr, out);
}